// round 6
// baseline (speedup 1.0000x reference)
#include <cuda_runtime.h>
#include <cstdint>

#define NN   50000
#define EMBD 256
#define NE   800000
#define ETOT (NE + NN)
#define NBLK 196                      // ceil(NN/256)

// ---------------- static device scratch ----------------
__device__ float g_h[(size_t)NN * EMBD];
__device__ float g_o1[(size_t)NN * EMBD];
__device__ float g_als[NN * 8];
__device__ float g_ald[NN * 8];
__device__ int   g_rowptr[NN + 1];
__device__ int   g_cnt[NN];
__device__ int   g_srcs[ETOT];
__device__ int   g_tmp[NN];
__device__ int   g_bsum[NBLK];
__device__ int   g_boff[NBLK];
__device__ int   g_is64;

__device__ __forceinline__ float lrelu(float x) { return x > 0.f ? x : 0.2f * x; }

__device__ __forceinline__ int edge_at(const void* ei, long long idx) {
    if (g_is64) return (int)((const long long*)ei)[idx];
    return ((const int*)ei)[idx];
}

__device__ __forceinline__ uint32_t f2tf(float f) {
    uint32_t u;
    asm("cvt.rna.tf32.f32 %0, %1;" : "=r"(u) : "f"(f));
    return u;
}

// ---------------- dtype probe ----------------
__global__ void detect_kernel(const void* ei) {
    const long long* p = (const long long*)ei;
    bool ok = true;
    #pragma unroll
    for (int i = 0; i < 8; i++) {
        long long v = p[i];
        if (v < 0 || v >= NN) ok = false;
    }
    g_is64 = ok ? 1 : 0;
}

// ---------------- CSR build ----------------
__global__ void zero_cnt_kernel() {
    int i = blockIdx.x * blockDim.x + threadIdx.x;
    if (i < NN) g_cnt[i] = 0;
}

__global__ void deg_kernel(const void* __restrict__ ei) {
    int e = blockIdx.x * blockDim.x + threadIdx.x;
    if (e < NE) atomicAdd(&g_cnt[edge_at(ei, (long long)NE + e)], 1);
}

__global__ void __launch_bounds__(256) scan1_kernel() {
    __shared__ int wsum[8];
    const int t = threadIdx.x, b = blockIdx.x;
    const int i = b * 256 + t;
    int v = (i < NN) ? g_cnt[i] + 1 : 0;
    int x = v;
    #pragma unroll
    for (int o = 1; o < 32; o <<= 1) {
        int y = __shfl_up_sync(0xffffffffu, x, o);
        if ((t & 31) >= o) x += y;
    }
    if ((t & 31) == 31) wsum[t >> 5] = x;
    __syncthreads();
    if (t < 8) {
        int w = wsum[t];
        #pragma unroll
        for (int o = 1; o < 8; o <<= 1) {
            int y = __shfl_up_sync(0xffu, w, o);
            if (t >= o) w += y;
        }
        wsum[t] = w;
    }
    __syncthreads();
    int incl = x + ((t >= 32) ? wsum[(t >> 5) - 1] : 0);
    if (i < NN) g_tmp[i] = incl;
    if (t == 255) g_bsum[b] = incl;
}

__global__ void __launch_bounds__(256) scan2_kernel() {
    __shared__ int wsum[8];
    const int t = threadIdx.x;
    int v = (t < NBLK) ? g_bsum[t] : 0;
    int x = v;
    #pragma unroll
    for (int o = 1; o < 32; o <<= 1) {
        int y = __shfl_up_sync(0xffffffffu, x, o);
        if ((t & 31) >= o) x += y;
    }
    if ((t & 31) == 31) wsum[t >> 5] = x;
    __syncthreads();
    if (t < 8) {
        int w = wsum[t];
        #pragma unroll
        for (int o = 1; o < 8; o <<= 1) {
            int y = __shfl_up_sync(0xffu, w, o);
            if (t >= o) w += y;
        }
        wsum[t] = w;
    }
    __syncthreads();
    int incl = x + ((t >= 32) ? wsum[(t >> 5) - 1] : 0);
    if (t < NBLK) g_boff[t] = incl - v;
    if (t == 0) g_rowptr[0] = 0;
}

__global__ void scan3_kernel() {
    int i = blockIdx.x * blockDim.x + threadIdx.x;
    if (i < NN) {
        g_rowptr[i + 1] = g_tmp[i] + g_boff[i >> 8];
        g_cnt[i] = 0;
    }
}

__global__ void scatter_kernel(const void* __restrict__ ei) {
    int e = blockIdx.x * blockDim.x + threadIdx.x;
    if (e < NE) {
        int s = edge_at(ei, e);
        int d = edge_at(ei, (long long)NE + e);
        int pos = g_rowptr[d] + atomicAdd(&g_cnt[d], 1);
        g_srcs[pos] = s;
    }
}

__global__ void self_kernel() {
    int i = blockIdx.x * blockDim.x + threadIdx.x;
    if (i < NN) g_srcs[g_rowptr[i + 1] - 1] = i;
}

// ---------------- tf32 tensor-core GEMM: g_h[M,256] = A[M,256] @ B[256,256] ----------------
template <bool INTERNAL_SRC>
__global__ void __launch_bounds__(256) gemm_tc_kernel(const float* __restrict__ Aext,
                                                      const float* __restrict__ B, int M) {
    const float* A = INTERNAL_SRC ? g_o1 : Aext;
    float* C = g_h;

    __shared__ uint32_t As[32][129];
    __shared__ uint32_t Bs[32][132];

    const int t    = threadIdx.x;
    const int lane = t & 31;
    const int w    = t >> 5;
    const int wr   = w & 3;
    const int wc   = w >> 2;
    const int tig  = lane & 3;
    const int gid  = lane >> 2;
    const int bm   = blockIdx.x * 128;
    const int bn   = blockIdx.y * 128;

    float acc[2][8][4];
    #pragma unroll
    for (int mt = 0; mt < 2; mt++)
        #pragma unroll
        for (int nt = 0; nt < 8; nt++)
            #pragma unroll
            for (int c = 0; c < 4; c++) acc[mt][nt][c] = 0.f;

    const int a_r  = t >> 3;
    const int a_ko = (t & 7) * 4;

    for (int kc = 0; kc < 8; kc++) {
        const int kbase = kc * 32;
        #pragma unroll
        for (int i = 0; i < 4; i++) {
            int r = a_r + i * 32;
            int grow = bm + r;
            float4 v = (grow < M) ? *(const float4*)(A + (size_t)grow * EMBD + kbase + a_ko)
                                  : make_float4(0.f, 0.f, 0.f, 0.f);
            As[a_ko + 0][r] = f2tf(v.x);
            As[a_ko + 1][r] = f2tf(v.y);
            As[a_ko + 2][r] = f2tf(v.z);
            As[a_ko + 3][r] = f2tf(v.w);
        }
        #pragma unroll
        for (int i = 0; i < 4; i++) {
            int idx  = t + i * 256;
            int kr   = idx >> 5;
            int c4   = (idx & 31) * 4;
            float4 v = *(const float4*)(B + (size_t)(kbase + kr) * EMBD + bn + c4);
            uint4 u;
            u.x = f2tf(v.x); u.y = f2tf(v.y); u.z = f2tf(v.z); u.w = f2tf(v.w);
            *(uint4*)&Bs[kr][c4] = u;
        }
        __syncthreads();

        #pragma unroll
        for (int k0 = 0; k0 < 32; k0 += 8) {
            uint32_t af[2][4], bf[8][2];
            const int kr0 = k0 + tig, kr1 = k0 + tig + 4;
            #pragma unroll
            for (int mt = 0; mt < 2; mt++) {
                int m0 = wr * 32 + mt * 16 + gid;
                af[mt][0] = As[kr0][m0];
                af[mt][1] = As[kr0][m0 + 8];
                af[mt][2] = As[kr1][m0];
                af[mt][3] = As[kr1][m0 + 8];
            }
            #pragma unroll
            for (int nt = 0; nt < 8; nt++) {
                int n0 = wc * 64 + nt * 8 + gid;
                bf[nt][0] = Bs[kr0][n0];
                bf[nt][1] = Bs[kr1][n0];
            }
            #pragma unroll
            for (int mt = 0; mt < 2; mt++)
                #pragma unroll
                for (int nt = 0; nt < 8; nt++) {
                    asm volatile(
                        "mma.sync.aligned.m16n8k8.row.col.f32.tf32.tf32.f32 "
                        "{%0,%1,%2,%3}, {%4,%5,%6,%7}, {%8,%9}, {%0,%1,%2,%3};\n"
                        : "+f"(acc[mt][nt][0]), "+f"(acc[mt][nt][1]),
                          "+f"(acc[mt][nt][2]), "+f"(acc[mt][nt][3])
                        : "r"(af[mt][0]), "r"(af[mt][1]), "r"(af[mt][2]), "r"(af[mt][3]),
                          "r"(bf[nt][0]), "r"(bf[nt][1]));
                }
        }
        __syncthreads();
    }

    #pragma unroll
    for (int mt = 0; mt < 2; mt++) {
        int row0 = bm + wr * 32 + mt * 16 + gid;
        #pragma unroll
        for (int nt = 0; nt < 8; nt++) {
            int col = bn + wc * 64 + nt * 8 + tig * 2;
            if (row0 < M)
                *(float2*)(C + (size_t)row0 * EMBD + col) = make_float2(acc[mt][nt][0], acc[mt][nt][1]);
            if (row0 + 8 < M)
                *(float2*)(C + (size_t)(row0 + 8) * EMBD + col) = make_float2(acc[mt][nt][2], acc[mt][nt][3]);
        }
    }
}

// ---------------- per-node attention logits ----------------
template <int H>
__global__ void al_kernel(const float* __restrict__ asrc,
                          const float* __restrict__ adst) {
    int n = blockIdx.x, t = threadIdx.x;
    float v  = g_h[(size_t)n * EMBD + t];
    float ps = v * asrc[t];
    float pd = v * adst[t];
    #pragma unroll
    for (int o = 16; o; o >>= 1) {
        ps += __shfl_xor_sync(0xffffffffu, ps, o);
        pd += __shfl_xor_sync(0xffffffffu, pd, o);
    }
    if (H == 8) {
        if ((t & 31) == 0) { g_als[n * 8 + (t >> 5)] = ps; g_ald[n * 8 + (t >> 5)] = pd; }
    } else {
        __shared__ float sps[8], spd[8];
        if ((t & 31) == 0) { sps[t >> 5] = ps; spd[t >> 5] = pd; }
        __syncthreads();
        if (t == 0) {
            float a = 0.f, b = 0.f;
            #pragma unroll
            for (int ww = 0; ww < 8; ww++) { a += sps[ww]; b += spd[ww]; }
            g_als[n] = a; g_ald[n] = b;
        }
    }
}

// ---------------- FUSED segment-softmax + aggregation (alpha cached in smem) ----------------
template <int H, bool INTERNAL_DST>
__global__ void __launch_bounds__(256) agg_fused_kernel(const float* __restrict__ bias,
                                                        float* __restrict__ outext) {
    constexpr int F     = EMBD / H;
    constexpr int CAP   = (H == 8) ? 512 : 4096;
    constexpr int GROUP = (H == 8) ? 32 : 256;
    __shared__ float lsh[H][CAP];      // logits, then converted in place to alpha
    __shared__ float red[8];
    __shared__ int   s_src[64];

    const int d = blockIdx.x, t = threadIdx.x;
    const int begin = g_rowptr[d], end = g_rowptr[d + 1];
    const int deg = end - begin;
    const int hh   = t / F;
    const int lane = (H == 8) ? (t & 31) : t;
    const float aldv = g_ald[d * H + hh];

    // ---- pass A: max ----
    float m = -1e30f;
    for (int i = lane; i < deg; i += GROUP) {
        int s = g_srcs[begin + i];
        float lg = lrelu(g_als[s * H + hh] + aldv);
        if (i < CAP) lsh[hh][i] = lg;
        m = fmaxf(m, lg);
    }
    #pragma unroll
    for (int o = 16; o; o >>= 1) m = fmaxf(m, __shfl_xor_sync(0xffffffffu, m, o));
    if (H == 1) {
        if ((t & 31) == 0) red[t >> 5] = m;
        __syncthreads();
        m = red[0];
        #pragma unroll
        for (int ww = 1; ww < 8; ww++) m = fmaxf(m, red[ww]);
        __syncthreads();
    }

    // ---- pass A: sum of exp ----
    float z = 0.f;
    for (int i = lane; i < deg; i += GROUP) {
        float lg = (i < CAP) ? lsh[hh][i]
                             : lrelu(g_als[g_srcs[begin + i] * H + hh] + aldv);
        z += __expf(lg - m);
    }
    #pragma unroll
    for (int o = 16; o; o >>= 1) z += __shfl_xor_sync(0xffffffffu, z, o);
    if (H == 1) {
        if ((t & 31) == 0) red[t >> 5] = z;
        __syncthreads();
        z = 0.f;
        #pragma unroll
        for (int ww = 0; ww < 8; ww++) z += red[ww];
    }
    const float inv = 1.f / (z + 1e-16f);

    // ---- convert cached logits to alpha in place (one exp per (edge, head)) ----
    {
        int lim = min(deg, CAP);
        for (int i = lane; i < lim; i += GROUP)
            lsh[hh][i] = __expf(lsh[hh][i] - m) * inv;
    }

    // ---- pass B: gather with alpha from smem ----
    float acc = 0.f;
    for (int c = begin; c < end; c += 64) {
        int len = min(64, end - c);
        __syncthreads();                 // also orders the in-place conversion for H=1
        if (t < len) s_src[t] = g_srcs[c + t];
        __syncthreads();
        #pragma unroll 4
        for (int j = 0; j < len; j++) {
            int i = (c - begin) + j;
            float alpha = (i < CAP) ? lsh[hh][i]
                                    : __expf(lrelu(g_als[s_src[j] * H + hh] + aldv) - m) * inv;
            acc += alpha * g_h[(size_t)s_src[j] * EMBD + t];
        }
    }
    float r = acc + bias[t];
    if (INTERNAL_DST) g_o1[(size_t)d * EMBD + t] = r;
    else              outext[(size_t)d * EMBD + t] = r;
}

// ---------------- launch ----------------
extern "C" void kernel_launch(void* const* d_in, const int* in_sizes, int n_in,
                              void* d_out, int out_size) {
    const float* x   = (const float*)d_in[0];
    const void*  ei  = d_in[1];
    const float* W1  = (const float*)d_in[2];
    const float* as1 = (const float*)d_in[3];
    const float* ad1 = (const float*)d_in[4];
    const float* b1  = (const float*)d_in[5];
    const float* W2  = (const float*)d_in[6];
    const float* as2 = (const float*)d_in[7];
    const float* ad2 = (const float*)d_in[8];
    const float* b2  = (const float*)d_in[9];
    float* out = (float*)d_out;

    detect_kernel<<<1, 1>>>(ei);

    zero_cnt_kernel<<<NBLK, 256>>>();
    deg_kernel<<<(NE + 255) / 256, 256>>>(ei);
    scan1_kernel<<<NBLK, 256>>>();
    scan2_kernel<<<1, 256>>>();
    scan3_kernel<<<NBLK, 256>>>();
    scatter_kernel<<<(NE + 255) / 256, 256>>>(ei);
    self_kernel<<<NBLK, 256>>>();

    dim3 gg((NN + 127) / 128, 2);

    // layer 1 (H=8, F=32)
    gemm_tc_kernel<false><<<gg, 256>>>(x, W1, NN);
    al_kernel<8><<<NN, 256>>>(as1, ad1);
    agg_fused_kernel<8, true><<<NN, 256>>>(b1, nullptr);

    // layer 2 (H=1, F=256)
    gemm_tc_kernel<true><<<gg, 256>>>(nullptr, W2, NN);
    al_kernel<1><<<NN, 256>>>(as2, ad2);
    agg_fused_kernel<1, false><<<NN, 256>>>(b2, out);
}

// round 7
// speedup vs baseline: 1.1471x; 1.1471x over previous
#include <cuda_runtime.h>
#include <cstdint>

#define NN   50000
#define EMBD 256
#define NE   800000
#define ETOT (NE + NN)
#define NBLK 196                      // ceil(NN/256)

// ---------------- static device scratch ----------------
__device__ float g_h[(size_t)NN * EMBD];
__device__ float g_o1[(size_t)NN * EMBD];
__device__ float g_als[NN * 8];
__device__ float g_ald[NN * 8];
__device__ float g_alpha[(size_t)ETOT * 8];
__device__ int   g_rowptr[NN + 1];
__device__ int   g_cnt[NN];
__device__ int   g_srcs[ETOT];
__device__ int   g_tmp[NN];
__device__ int   g_bsum[NBLK];
__device__ int   g_boff[NBLK];
__device__ int   g_is64;

__device__ __forceinline__ float lrelu(float x) { return x > 0.f ? x : 0.2f * x; }

__device__ __forceinline__ int edge_at(const void* ei, long long idx) {
    if (g_is64) return (int)((const long long*)ei)[idx];
    return ((const int*)ei)[idx];
}

__device__ __forceinline__ uint32_t f2tf(float f) {
    uint32_t u;
    asm("cvt.rna.tf32.f32 %0, %1;" : "=r"(u) : "f"(f));
    return u;
}

// ---------------- zero counters + dtype probe (merged) ----------------
__global__ void zero_detect_kernel(const void* ei) {
    int i = blockIdx.x * blockDim.x + threadIdx.x;
    if (i < NN) g_cnt[i] = 0;
    if (i == 0) {
        const long long* p = (const long long*)ei;
        bool ok = true;
        #pragma unroll
        for (int k = 0; k < 8; k++) {
            long long v = p[k];
            if (v < 0 || v >= NN) ok = false;
        }
        g_is64 = ok ? 1 : 0;
    }
}

// ---------------- CSR build ----------------
__global__ void deg_kernel(const void* __restrict__ ei) {
    int e = blockIdx.x * blockDim.x + threadIdx.x;
    if (e < NE) atomicAdd(&g_cnt[edge_at(ei, (long long)NE + e)], 1);
}

__global__ void __launch_bounds__(256) scan1_kernel() {
    __shared__ int wsum[8];
    const int t = threadIdx.x, b = blockIdx.x;
    const int i = b * 256 + t;
    int v = (i < NN) ? g_cnt[i] + 1 : 0;
    int x = v;
    #pragma unroll
    for (int o = 1; o < 32; o <<= 1) {
        int y = __shfl_up_sync(0xffffffffu, x, o);
        if ((t & 31) >= o) x += y;
    }
    if ((t & 31) == 31) wsum[t >> 5] = x;
    __syncthreads();
    if (t < 8) {
        int w = wsum[t];
        #pragma unroll
        for (int o = 1; o < 8; o <<= 1) {
            int y = __shfl_up_sync(0xffu, w, o);
            if (t >= o) w += y;
        }
        wsum[t] = w;
    }
    __syncthreads();
    int incl = x + ((t >= 32) ? wsum[(t >> 5) - 1] : 0);
    if (i < NN) g_tmp[i] = incl;
    if (t == 255) g_bsum[b] = incl;
}

__global__ void __launch_bounds__(256) scan2_kernel() {
    __shared__ int wsum[8];
    const int t = threadIdx.x;
    int v = (t < NBLK) ? g_bsum[t] : 0;
    int x = v;
    #pragma unroll
    for (int o = 1; o < 32; o <<= 1) {
        int y = __shfl_up_sync(0xffffffffu, x, o);
        if ((t & 31) >= o) x += y;
    }
    if ((t & 31) == 31) wsum[t >> 5] = x;
    __syncthreads();
    if (t < 8) {
        int w = wsum[t];
        #pragma unroll
        for (int o = 1; o < 8; o <<= 1) {
            int y = __shfl_up_sync(0xffu, w, o);
            if (t >= o) w += y;
        }
        wsum[t] = w;
    }
    __syncthreads();
    int incl = x + ((t >= 32) ? wsum[(t >> 5) - 1] : 0);
    if (t < NBLK) g_boff[t] = incl - v;
    if (t == 0) g_rowptr[0] = 0;
}

__global__ void scan3_kernel() {
    int i = blockIdx.x * blockDim.x + threadIdx.x;
    if (i < NN) {
        g_rowptr[i + 1] = g_tmp[i] + g_boff[i >> 8];
        g_cnt[i] = 0;
    }
}

__global__ void scatter_kernel(const void* __restrict__ ei) {
    int e = blockIdx.x * blockDim.x + threadIdx.x;
    if (e < NE) {
        int s = edge_at(ei, e);
        int d = edge_at(ei, (long long)NE + e);
        int pos = g_rowptr[d] + atomicAdd(&g_cnt[d], 1);
        g_srcs[pos] = s;
    }
}

__global__ void self_kernel() {
    int i = blockIdx.x * blockDim.x + threadIdx.x;
    if (i < NN) g_srcs[g_rowptr[i + 1] - 1] = i;
}

// ---------------- tf32 tensor-core GEMM with register-prefetch pipeline ----------------
template <bool INTERNAL_SRC>
__global__ void __launch_bounds__(256) gemm_tc_kernel(const float* __restrict__ Aext,
                                                      const float* __restrict__ B, int M) {
    const float* A = INTERNAL_SRC ? g_o1 : Aext;
    float* C = g_h;

    __shared__ uint32_t As[32][129];
    __shared__ uint32_t Bs[32][132];

    const int t    = threadIdx.x;
    const int lane = t & 31;
    const int w    = t >> 5;
    const int wr   = w & 3;
    const int wc   = w >> 2;
    const int tig  = lane & 3;
    const int gid  = lane >> 2;
    const int bm   = blockIdx.x * 128;
    const int bn   = blockIdx.y * 128;

    float acc[2][8][4];
    #pragma unroll
    for (int mt = 0; mt < 2; mt++)
        #pragma unroll
        for (int nt = 0; nt < 8; nt++)
            #pragma unroll
            for (int c = 0; c < 4; c++) acc[mt][nt][c] = 0.f;

    const int a_r  = t >> 3;
    const int a_ko = (t & 7) * 4;
    const int b_kr = t >> 5;           // via idx decomposition below

    float4 pa[4], pb[4];

    // initial prefetch: chunk 0
    #pragma unroll
    for (int i = 0; i < 4; i++) {
        int grow = bm + a_r + i * 32;
        pa[i] = (grow < M) ? *(const float4*)(A + (size_t)grow * EMBD + a_ko)
                           : make_float4(0.f, 0.f, 0.f, 0.f);
    }
    #pragma unroll
    for (int i = 0; i < 4; i++) {
        int idx = t + i * 256;
        int kr  = idx >> 5;
        int c4  = (idx & 31) * 4;
        pb[i] = *(const float4*)(B + (size_t)kr * EMBD + bn + c4);
    }

    for (int kc = 0; kc < 8; kc++) {
        // stage prefetched chunk to smem (with tf32 conversion)
        #pragma unroll
        for (int i = 0; i < 4; i++) {
            int r = a_r + i * 32;
            As[a_ko + 0][r] = f2tf(pa[i].x);
            As[a_ko + 1][r] = f2tf(pa[i].y);
            As[a_ko + 2][r] = f2tf(pa[i].z);
            As[a_ko + 3][r] = f2tf(pa[i].w);
        }
        #pragma unroll
        for (int i = 0; i < 4; i++) {
            int idx = t + i * 256;
            int kr  = idx >> 5;
            int c4  = (idx & 31) * 4;
            uint4 u;
            u.x = f2tf(pb[i].x); u.y = f2tf(pb[i].y); u.z = f2tf(pb[i].z); u.w = f2tf(pb[i].w);
            *(uint4*)&Bs[kr][c4] = u;
        }
        __syncthreads();

        // prefetch next chunk from gmem (overlaps with mma below)
        if (kc + 1 < 8) {
            const int kbase = (kc + 1) * 32;
            #pragma unroll
            for (int i = 0; i < 4; i++) {
                int grow = bm + a_r + i * 32;
                pa[i] = (grow < M) ? *(const float4*)(A + (size_t)grow * EMBD + kbase + a_ko)
                                   : make_float4(0.f, 0.f, 0.f, 0.f);
            }
            #pragma unroll
            for (int i = 0; i < 4; i++) {
                int idx = t + i * 256;
                int kr  = idx >> 5;
                int c4  = (idx & 31) * 4;
                pb[i] = *(const float4*)(B + (size_t)(kbase + kr) * EMBD + bn + c4);
            }
        }

        #pragma unroll
        for (int k0 = 0; k0 < 32; k0 += 8) {
            uint32_t af[2][4], bf[8][2];
            const int kr0 = k0 + tig, kr1 = k0 + tig + 4;
            #pragma unroll
            for (int mt = 0; mt < 2; mt++) {
                int m0 = wr * 32 + mt * 16 + gid;
                af[mt][0] = As[kr0][m0];
                af[mt][1] = As[kr0][m0 + 8];
                af[mt][2] = As[kr1][m0];
                af[mt][3] = As[kr1][m0 + 8];
            }
            #pragma unroll
            for (int nt = 0; nt < 8; nt++) {
                int n0 = wc * 64 + nt * 8 + gid;
                bf[nt][0] = Bs[kr0][n0];
                bf[nt][1] = Bs[kr1][n0];
            }
            #pragma unroll
            for (int mt = 0; mt < 2; mt++)
                #pragma unroll
                for (int nt = 0; nt < 8; nt++) {
                    asm volatile(
                        "mma.sync.aligned.m16n8k8.row.col.f32.tf32.tf32.f32 "
                        "{%0,%1,%2,%3}, {%4,%5,%6,%7}, {%8,%9}, {%0,%1,%2,%3};\n"
                        : "+f"(acc[mt][nt][0]), "+f"(acc[mt][nt][1]),
                          "+f"(acc[mt][nt][2]), "+f"(acc[mt][nt][3])
                        : "r"(af[mt][0]), "r"(af[mt][1]), "r"(af[mt][2]), "r"(af[mt][3]),
                          "r"(bf[nt][0]), "r"(bf[nt][1]));
                }
        }
        __syncthreads();
    }

    #pragma unroll
    for (int mt = 0; mt < 2; mt++) {
        int row0 = bm + wr * 32 + mt * 16 + gid;
        #pragma unroll
        for (int nt = 0; nt < 8; nt++) {
            int col = bn + wc * 64 + nt * 8 + tig * 2;
            if (row0 < M)
                *(float2*)(C + (size_t)row0 * EMBD + col) = make_float2(acc[mt][nt][0], acc[mt][nt][1]);
            if (row0 + 8 < M)
                *(float2*)(C + (size_t)(row0 + 8) * EMBD + col) = make_float2(acc[mt][nt][2], acc[mt][nt][3]);
        }
    }
}

// ---------------- per-node attention logits ----------------
template <int H>
__global__ void al_kernel(const float* __restrict__ asrc,
                          const float* __restrict__ adst) {
    int n = blockIdx.x, t = threadIdx.x;
    float v  = g_h[(size_t)n * EMBD + t];
    float ps = v * asrc[t];
    float pd = v * adst[t];
    #pragma unroll
    for (int o = 16; o; o >>= 1) {
        ps += __shfl_xor_sync(0xffffffffu, ps, o);
        pd += __shfl_xor_sync(0xffffffffu, pd, o);
    }
    if (H == 8) {
        if ((t & 31) == 0) { g_als[n * 8 + (t >> 5)] = ps; g_ald[n * 8 + (t >> 5)] = pd; }
    } else {
        __shared__ float sps[8], spd[8];
        if ((t & 31) == 0) { sps[t >> 5] = ps; spd[t >> 5] = pd; }
        __syncthreads();
        if (t == 0) {
            float a = 0.f, b = 0.f;
            #pragma unroll
            for (int ww = 0; ww < 8; ww++) { a += sps[ww]; b += spd[ww]; }
            g_als[n] = a; g_ald[n] = b;
        }
    }
}

// ---------------- segment softmax ----------------
template <int H>
__global__ void __launch_bounds__(256) softmax_kernel() {
    constexpr int CAP   = (H == 8) ? 512 : 4096;
    constexpr int GROUP = (H == 8) ? 32 : 256;
    __shared__ float lsh[H][CAP];
    __shared__ float red[8];

    const int d = blockIdx.x;
    const int begin = g_rowptr[d], end = g_rowptr[d + 1];
    const int deg = end - begin;
    const int hh   = (H == 8) ? (threadIdx.x >> 5) : 0;
    const int lane = (H == 8) ? (threadIdx.x & 31) : threadIdx.x;
    const float aldv = g_ald[d * H + hh];

    float m = -1e30f;
    for (int i = lane; i < deg; i += GROUP) {
        int s = __ldg(&g_srcs[begin + i]);
        float lg = lrelu(__ldg(&g_als[s * H + hh]) + aldv);
        if (i < CAP) lsh[hh][i] = lg;
        m = fmaxf(m, lg);
    }
    #pragma unroll
    for (int o = 16; o; o >>= 1) m = fmaxf(m, __shfl_xor_sync(0xffffffffu, m, o));
    if (H == 1) {
        if ((threadIdx.x & 31) == 0) red[threadIdx.x >> 5] = m;
        __syncthreads();
        m = red[0];
        #pragma unroll
        for (int ww = 1; ww < 8; ww++) m = fmaxf(m, red[ww]);
        __syncthreads();
    }

    float z = 0.f;
    for (int i = lane; i < deg; i += GROUP) {
        float lg = (i < CAP) ? lsh[hh][i]
                             : lrelu(__ldg(&g_als[__ldg(&g_srcs[begin + i]) * H + hh]) + aldv);
        z += __expf(lg - m);
    }
    #pragma unroll
    for (int o = 16; o; o >>= 1) z += __shfl_xor_sync(0xffffffffu, z, o);
    if (H == 1) {
        if ((threadIdx.x & 31) == 0) red[threadIdx.x >> 5] = z;
        __syncthreads();
        z = 0.f;
        #pragma unroll
        for (int ww = 0; ww < 8; ww++) z += red[ww];
    }

    const float inv = 1.f / (z + 1e-16f);
    for (int i = lane; i < deg; i += GROUP) {
        float lg = (i < CAP) ? lsh[hh][i]
                             : lrelu(__ldg(&g_als[__ldg(&g_srcs[begin + i]) * H + hh]) + aldv);
        g_alpha[(size_t)(begin + i) * H + hh] = __expf(lg - m) * inv;
    }
}

// ---------------- aggregation ----------------
template <int H, bool INTERNAL_DST>
__global__ void __launch_bounds__(256) agg_kernel(const float* __restrict__ bias,
                                                  float* __restrict__ outext) {
    constexpr int F = EMBD / H;
    const int d = blockIdx.x, t = threadIdx.x;
    const int hh = t / F;
    const int begin = g_rowptr[d], end = g_rowptr[d + 1];

    __shared__ int   s_src[64];
    __shared__ float s_alpha[64 * H];

    float acc = 0.f;
    for (int c = begin; c < end; c += 64) {
        int len = min(64, end - c);
        __syncthreads();
        if (t < len) s_src[t] = g_srcs[c + t];
        for (int i = t; i < len * H; i += 256) s_alpha[i] = g_alpha[(size_t)c * H + i];
        __syncthreads();
        #pragma unroll 4
        for (int j = 0; j < len; j++)
            acc += s_alpha[j * H + hh] * __ldg(&g_h[(size_t)s_src[j] * EMBD + t]);
    }
    float r = acc + bias[t];
    if (INTERNAL_DST) g_o1[(size_t)d * EMBD + t] = r;
    else              outext[(size_t)d * EMBD + t] = r;
}

// ---------------- launch ----------------
extern "C" void kernel_launch(void* const* d_in, const int* in_sizes, int n_in,
                              void* d_out, int out_size) {
    const float* x   = (const float*)d_in[0];
    const void*  ei  = d_in[1];
    const float* W1  = (const float*)d_in[2];
    const float* as1 = (const float*)d_in[3];
    const float* ad1 = (const float*)d_in[4];
    const float* b1  = (const float*)d_in[5];
    const float* W2  = (const float*)d_in[6];
    const float* as2 = (const float*)d_in[7];
    const float* ad2 = (const float*)d_in[8];
    const float* b2  = (const float*)d_in[9];
    float* out = (float*)d_out;

    zero_detect_kernel<<<NBLK, 256>>>(ei);
    deg_kernel<<<(NE + 255) / 256, 256>>>(ei);
    scan1_kernel<<<NBLK, 256>>>();
    scan2_kernel<<<1, 256>>>();
    scan3_kernel<<<NBLK, 256>>>();
    scatter_kernel<<<(NE + 255) / 256, 256>>>(ei);
    self_kernel<<<NBLK, 256>>>();

    dim3 gg((NN + 127) / 128, 2);

    // layer 1 (H=8, F=32)
    gemm_tc_kernel<false><<<gg, 256>>>(x, W1, NN);
    al_kernel<8><<<NN, 256>>>(as1, ad1);
    softmax_kernel<8><<<NN, 256>>>();
    agg_kernel<8, true><<<NN, 256>>>(b1, nullptr);

    // layer 2 (H=1, F=256)
    gemm_tc_kernel<true><<<gg, 256>>>(nullptr, W2, NN);
    al_kernel<1><<<NN, 256>>>(as2, ad2);
    softmax_kernel<1><<<NN, 256>>>();
    agg_kernel<1, false><<<NN, 256>>>(b2, out);
}

// round 8
// speedup vs baseline: 1.2915x; 1.1258x over previous
#include <cuda_runtime.h>
#include <cstdint>

#define NN   50000
#define EMBD 256
#define NE   800000
#define ETOT (NE + NN)
#define NBLK 196                      // ceil(NN/256)

// ---------------- static device scratch ----------------
__device__ float g_h[(size_t)NN * EMBD];
__device__ float g_o1[(size_t)NN * EMBD];
__device__ float g_als[NN * 8];
__device__ float g_ald[NN * 8];
__device__ float g_alpha[(size_t)ETOT * 8];   // unnormalized exp(logit)
__device__ float g_z[NN * 8];                 // segment sums
__device__ int   g_rowptr[NN + 1];
__device__ int   g_cnt[NN];
__device__ int   g_srcs[ETOT];
__device__ int   g_tmp[NN];
__device__ int   g_bsum[NBLK];
__device__ int   g_boff[NBLK];
__device__ int   g_is64;

__device__ __forceinline__ float lrelu(float x) { return x > 0.f ? x : 0.2f * x; }

__device__ __forceinline__ int edge_at(const void* ei, long long idx) {
    if (g_is64) return (int)((const long long*)ei)[idx];
    return ((const int*)ei)[idx];
}

__device__ __forceinline__ uint32_t f2tf(float f) {
    uint32_t u;
    asm("cvt.rna.tf32.f32 %0, %1;" : "=r"(u) : "f"(f));
    return u;
}

// ---------------- zero counters + dtype probe (merged) ----------------
__global__ void zero_detect_kernel(const void* ei) {
    int i = blockIdx.x * blockDim.x + threadIdx.x;
    if (i < NN) g_cnt[i] = 0;
    if (i == 0) {
        const long long* p = (const long long*)ei;
        bool ok = true;
        #pragma unroll
        for (int k = 0; k < 8; k++) {
            long long v = p[k];
            if (v < 0 || v >= NN) ok = false;
        }
        g_is64 = ok ? 1 : 0;
    }
}

// ---------------- CSR build ----------------
__global__ void deg_kernel(const void* __restrict__ ei) {
    int e = blockIdx.x * blockDim.x + threadIdx.x;
    if (e < NE) atomicAdd(&g_cnt[edge_at(ei, (long long)NE + e)], 1);
}

__global__ void __launch_bounds__(256) scan1_kernel() {
    __shared__ int wsum[8];
    const int t = threadIdx.x, b = blockIdx.x;
    const int i = b * 256 + t;
    int v = (i < NN) ? g_cnt[i] + 1 : 0;
    int x = v;
    #pragma unroll
    for (int o = 1; o < 32; o <<= 1) {
        int y = __shfl_up_sync(0xffffffffu, x, o);
        if ((t & 31) >= o) x += y;
    }
    if ((t & 31) == 31) wsum[t >> 5] = x;
    __syncthreads();
    if (t < 8) {
        int w = wsum[t];
        #pragma unroll
        for (int o = 1; o < 8; o <<= 1) {
            int y = __shfl_up_sync(0xffu, w, o);
            if (t >= o) w += y;
        }
        wsum[t] = w;
    }
    __syncthreads();
    int incl = x + ((t >= 32) ? wsum[(t >> 5) - 1] : 0);
    if (i < NN) g_tmp[i] = incl;
    if (t == 255) g_bsum[b] = incl;
}

__global__ void __launch_bounds__(256) scan2_kernel() {
    __shared__ int wsum[8];
    const int t = threadIdx.x;
    int v = (t < NBLK) ? g_bsum[t] : 0;
    int x = v;
    #pragma unroll
    for (int o = 1; o < 32; o <<= 1) {
        int y = __shfl_up_sync(0xffffffffu, x, o);
        if ((t & 31) >= o) x += y;
    }
    if ((t & 31) == 31) wsum[t >> 5] = x;
    __syncthreads();
    if (t < 8) {
        int w = wsum[t];
        #pragma unroll
        for (int o = 1; o < 8; o <<= 1) {
            int y = __shfl_up_sync(0xffu, w, o);
            if (t >= o) w += y;
        }
        wsum[t] = w;
    }
    __syncthreads();
    int incl = x + ((t >= 32) ? wsum[(t >> 5) - 1] : 0);
    if (t < NBLK) g_boff[t] = incl - v;
    if (t == 0) g_rowptr[0] = 0;
}

// phase 3: offsets -> rowptr; zero cnt; place self-loop at segment end
__global__ void scan3_kernel() {
    int i = blockIdx.x * blockDim.x + threadIdx.x;
    if (i < NN) {
        int rp1 = g_tmp[i] + g_boff[i >> 8];
        g_rowptr[i + 1] = rp1;
        g_cnt[i] = 0;
        g_srcs[rp1 - 1] = i;
    }
}

__global__ void scatter_kernel(const void* __restrict__ ei) {
    int e = blockIdx.x * blockDim.x + threadIdx.x;
    if (e < NE) {
        int s = edge_at(ei, e);
        int d = edge_at(ei, (long long)NE + e);
        int pos = g_rowptr[d] + atomicAdd(&g_cnt[d], 1);
        g_srcs[pos] = s;
    }
}

// ---------------- tf32 tensor-core GEMM with register-prefetch pipeline ----------------
template <bool INTERNAL_SRC>
__global__ void __launch_bounds__(256) gemm_tc_kernel(const float* __restrict__ Aext,
                                                      const float* __restrict__ B, int M) {
    const float* A = INTERNAL_SRC ? g_o1 : Aext;
    float* C = g_h;

    __shared__ uint32_t As[32][129];
    __shared__ uint32_t Bs[32][132];

    const int t    = threadIdx.x;
    const int lane = t & 31;
    const int w    = t >> 5;
    const int wr   = w & 3;
    const int wc   = w >> 2;
    const int tig  = lane & 3;
    const int gid  = lane >> 2;
    const int bm   = blockIdx.x * 128;
    const int bn   = blockIdx.y * 128;

    float acc[2][8][4];
    #pragma unroll
    for (int mt = 0; mt < 2; mt++)
        #pragma unroll
        for (int nt = 0; nt < 8; nt++)
            #pragma unroll
            for (int c = 0; c < 4; c++) acc[mt][nt][c] = 0.f;

    const int a_r  = t >> 3;
    const int a_ko = (t & 7) * 4;

    float4 pa[4], pb[4];

    #pragma unroll
    for (int i = 0; i < 4; i++) {
        int grow = bm + a_r + i * 32;
        pa[i] = (grow < M) ? *(const float4*)(A + (size_t)grow * EMBD + a_ko)
                           : make_float4(0.f, 0.f, 0.f, 0.f);
    }
    #pragma unroll
    for (int i = 0; i < 4; i++) {
        int idx = t + i * 256;
        int kr  = idx >> 5;
        int c4  = (idx & 31) * 4;
        pb[i] = *(const float4*)(B + (size_t)kr * EMBD + bn + c4);
    }

    for (int kc = 0; kc < 8; kc++) {
        #pragma unroll
        for (int i = 0; i < 4; i++) {
            int r = a_r + i * 32;
            As[a_ko + 0][r] = f2tf(pa[i].x);
            As[a_ko + 1][r] = f2tf(pa[i].y);
            As[a_ko + 2][r] = f2tf(pa[i].z);
            As[a_ko + 3][r] = f2tf(pa[i].w);
        }
        #pragma unroll
        for (int i = 0; i < 4; i++) {
            int idx = t + i * 256;
            int kr  = idx >> 5;
            int c4  = (idx & 31) * 4;
            uint4 u;
            u.x = f2tf(pb[i].x); u.y = f2tf(pb[i].y); u.z = f2tf(pb[i].z); u.w = f2tf(pb[i].w);
            *(uint4*)&Bs[kr][c4] = u;
        }
        __syncthreads();

        if (kc + 1 < 8) {
            const int kbase = (kc + 1) * 32;
            #pragma unroll
            for (int i = 0; i < 4; i++) {
                int grow = bm + a_r + i * 32;
                pa[i] = (grow < M) ? *(const float4*)(A + (size_t)grow * EMBD + kbase + a_ko)
                                   : make_float4(0.f, 0.f, 0.f, 0.f);
            }
            #pragma unroll
            for (int i = 0; i < 4; i++) {
                int idx = t + i * 256;
                int kr  = idx >> 5;
                int c4  = (idx & 31) * 4;
                pb[i] = *(const float4*)(B + (size_t)(kbase + kr) * EMBD + bn + c4);
            }
        }

        #pragma unroll
        for (int k0 = 0; k0 < 32; k0 += 8) {
            uint32_t af[2][4], bf[8][2];
            const int kr0 = k0 + tig, kr1 = k0 + tig + 4;
            #pragma unroll
            for (int mt = 0; mt < 2; mt++) {
                int m0 = wr * 32 + mt * 16 + gid;
                af[mt][0] = As[kr0][m0];
                af[mt][1] = As[kr0][m0 + 8];
                af[mt][2] = As[kr1][m0];
                af[mt][3] = As[kr1][m0 + 8];
            }
            #pragma unroll
            for (int nt = 0; nt < 8; nt++) {
                int n0 = wc * 64 + nt * 8 + gid;
                bf[nt][0] = Bs[kr0][n0];
                bf[nt][1] = Bs[kr1][n0];
            }
            #pragma unroll
            for (int mt = 0; mt < 2; mt++)
                #pragma unroll
                for (int nt = 0; nt < 8; nt++) {
                    asm volatile(
                        "mma.sync.aligned.m16n8k8.row.col.f32.tf32.tf32.f32 "
                        "{%0,%1,%2,%3}, {%4,%5,%6,%7}, {%8,%9}, {%0,%1,%2,%3};\n"
                        : "+f"(acc[mt][nt][0]), "+f"(acc[mt][nt][1]),
                          "+f"(acc[mt][nt][2]), "+f"(acc[mt][nt][3])
                        : "r"(af[mt][0]), "r"(af[mt][1]), "r"(af[mt][2]), "r"(af[mt][3]),
                          "r"(bf[nt][0]), "r"(bf[nt][1]));
                }
        }
        __syncthreads();
    }

    #pragma unroll
    for (int mt = 0; mt < 2; mt++) {
        int row0 = bm + wr * 32 + mt * 16 + gid;
        #pragma unroll
        for (int nt = 0; nt < 8; nt++) {
            int col = bn + wc * 64 + nt * 8 + tig * 2;
            if (row0 < M)
                *(float2*)(C + (size_t)row0 * EMBD + col) = make_float2(acc[mt][nt][0], acc[mt][nt][1]);
            if (row0 + 8 < M)
                *(float2*)(C + (size_t)(row0 + 8) * EMBD + col) = make_float2(acc[mt][nt][2], acc[mt][nt][3]);
        }
    }
}

// ---------------- per-node attention logits (warp per node, 8 nodes/block) ----------------
template <int H>
__global__ void __launch_bounds__(256) al_kernel(const float* __restrict__ asrc,
                                                 const float* __restrict__ adst) {
    const int t = threadIdx.x;
    const int lane = t & 31;
    const int n = blockIdx.x * 8 + (t >> 5);
    if (n >= NN) return;

    const float* row = g_h + (size_t)n * EMBD + lane * 8;
    float4 v0 = *(const float4*)(row);
    float4 v1 = *(const float4*)(row + 4);
    const float* as = asrc + lane * 8;
    const float* ad = adst + lane * 8;
    float4 s0 = *(const float4*)(as);
    float4 s1 = *(const float4*)(as + 4);
    float4 d0 = *(const float4*)(ad);
    float4 d1 = *(const float4*)(ad + 4);

    float ps = v0.x*s0.x + v0.y*s0.y + v0.z*s0.z + v0.w*s0.w
             + v1.x*s1.x + v1.y*s1.y + v1.z*s1.z + v1.w*s1.w;
    float pd = v0.x*d0.x + v0.y*d0.y + v0.z*d0.z + v0.w*d0.w
             + v1.x*d1.x + v1.y*d1.y + v1.z*d1.z + v1.w*d1.w;

    if (H == 8) {
        // lanes 4h..4h+3 cover head h (elements [h*32,(h+1)*32))
        #pragma unroll
        for (int o = 1; o < 4; o <<= 1) {
            ps += __shfl_xor_sync(0xffffffffu, ps, o);
            pd += __shfl_xor_sync(0xffffffffu, pd, o);
        }
        if ((lane & 3) == 0) {
            g_als[n * 8 + (lane >> 2)] = ps;
            g_ald[n * 8 + (lane >> 2)] = pd;
        }
    } else {
        #pragma unroll
        for (int o = 16; o; o >>= 1) {
            ps += __shfl_xor_sync(0xffffffffu, ps, o);
            pd += __shfl_xor_sync(0xffffffffu, pd, o);
        }
        if (lane == 0) { g_als[n] = ps; g_ald[n] = pd; }
    }
}

// ---------------- unnormalized exp + segment sum (single edge walk) ----------------
template <int H>
__global__ void __launch_bounds__(256) expsum_kernel() {
    const int d = blockIdx.x, t = threadIdx.x;
    const int begin = g_rowptr[d], end = g_rowptr[d + 1];
    const int deg = end - begin;

    if (H == 8) {
        const int hh = t >> 5, lane = t & 31;
        const float aldv = g_ald[d * 8 + hh];
        float z = 0.f;
        for (int i = lane; i < deg; i += 32) {
            int s = __ldg(&g_srcs[begin + i]);
            float e = __expf(lrelu(__ldg(&g_als[s * 8 + hh]) + aldv));
            g_alpha[(size_t)(begin + i) * 8 + hh] = e;
            z += e;
        }
        #pragma unroll
        for (int o = 16; o; o >>= 1) z += __shfl_xor_sync(0xffffffffu, z, o);
        if (lane == 0) g_z[d * 8 + hh] = z;
    } else {
        __shared__ float red[8];
        const float aldv = g_ald[d];
        float z = 0.f;
        for (int i = t; i < deg; i += 256) {
            int s = __ldg(&g_srcs[begin + i]);
            float e = __expf(lrelu(__ldg(&g_als[s]) + aldv));
            g_alpha[(size_t)(begin + i) * H + 0] = e;   // H==1 layout
            z += e;
        }
        #pragma unroll
        for (int o = 16; o; o >>= 1) z += __shfl_xor_sync(0xffffffffu, z, o);
        if ((t & 31) == 0) red[t >> 5] = z;
        __syncthreads();
        if (t == 0) {
            float zz = 0.f;
            #pragma unroll
            for (int ww = 0; ww < 8; ww++) zz += red[ww];
            g_z[d] = zz;
        }
    }
}

// ---------------- aggregation (normalizes by z in epilogue) ----------------
template <int H, bool INTERNAL_DST>
__global__ void __launch_bounds__(256) agg_kernel(const float* __restrict__ bias,
                                                  float* __restrict__ outext) {
    constexpr int F = EMBD / H;
    const int d = blockIdx.x, t = threadIdx.x;
    const int hh = t / F;
    const int begin = g_rowptr[d], end = g_rowptr[d + 1];

    __shared__ int   s_src[64];
    __shared__ float s_alpha[64 * H];

    float acc = 0.f;
    for (int c = begin; c < end; c += 64) {
        int len = min(64, end - c);
        __syncthreads();
        if (t < len) s_src[t] = g_srcs[c + t];
        for (int i = t; i < len * H; i += 256) s_alpha[i] = g_alpha[(size_t)c * H + i];
        __syncthreads();
        #pragma unroll 4
        for (int j = 0; j < len; j++)
            acc += s_alpha[j * H + hh] * __ldg(&g_h[(size_t)s_src[j] * EMBD + t]);
    }
    float inv = 1.f / (g_z[d * H + hh] + 1e-16f);
    float r = acc * inv + bias[t];
    if (INTERNAL_DST) g_o1[(size_t)d * EMBD + t] = r;
    else              outext[(size_t)d * EMBD + t] = r;
}

// ---------------- launch ----------------
extern "C" void kernel_launch(void* const* d_in, const int* in_sizes, int n_in,
                              void* d_out, int out_size) {
    const float* x   = (const float*)d_in[0];
    const void*  ei  = d_in[1];
    const float* W1  = (const float*)d_in[2];
    const float* as1 = (const float*)d_in[3];
    const float* ad1 = (const float*)d_in[4];
    const float* b1  = (const float*)d_in[5];
    const float* W2  = (const float*)d_in[6];
    const float* as2 = (const float*)d_in[7];
    const float* ad2 = (const float*)d_in[8];
    const float* b2  = (const float*)d_in[9];
    float* out = (float*)d_out;

    zero_detect_kernel<<<NBLK, 256>>>(ei);
    deg_kernel<<<(NE + 255) / 256, 256>>>(ei);
    scan1_kernel<<<NBLK, 256>>>();
    scan2_kernel<<<1, 256>>>();
    scan3_kernel<<<NBLK, 256>>>();
    scatter_kernel<<<(NE + 255) / 256, 256>>>(ei);

    dim3 gg((NN + 127) / 128, 2);
    const int ALB = (NN + 7) / 8;

    // layer 1 (H=8, F=32)
    gemm_tc_kernel<false><<<gg, 256>>>(x, W1, NN);
    al_kernel<8><<<ALB, 256>>>(as1, ad1);
    expsum_kernel<8><<<NN, 256>>>();
    agg_kernel<8, true><<<NN, 256>>>(b1, nullptr);

    // layer 2 (H=1, F=256)
    gemm_tc_kernel<true><<<gg, 256>>>(nullptr, W2, NN);
    al_kernel<1><<<ALB, 256>>>(as2, ad2);
    expsum_kernel<1><<<NN, 256>>>();
    agg_kernel<1, false><<<NN, 256>>>(b2, out);
}

// round 9
// speedup vs baseline: 1.6320x; 1.2636x over previous
#include <cuda_runtime.h>
#include <cstdint>

#define NN   50000
#define EMBD 256
#define NE   800000
#define ETOT (NE + NN)
#define NBLK 196                      // ceil(NN/256)

// ---------------- static device scratch ----------------
__device__ float g_h[(size_t)NN * EMBD];
__device__ float g_o1[(size_t)NN * EMBD];
__device__ float g_als[NN * 8];
__device__ float g_ald[NN * 8];
__device__ int   g_rowptr[NN + 1];
__device__ int   g_cnt[NN];
__device__ int   g_srcs[ETOT];
__device__ int   g_tmp[NN];
__device__ int   g_bsum[NBLK];
__device__ int   g_boff[NBLK];
__device__ int   g_is64;

__device__ __forceinline__ float lrelu(float x) { return x > 0.f ? x : 0.2f * x; }

__device__ __forceinline__ int edge_at(const void* ei, long long idx) {
    if (g_is64) return (int)((const long long*)ei)[idx];
    return ((const int*)ei)[idx];
}

__device__ __forceinline__ uint32_t f2tf(float f) {
    uint32_t u;
    asm("cvt.rna.tf32.f32 %0, %1;" : "=r"(u) : "f"(f));
    return u;
}

// ---------------- zero counters + dtype probe (merged) ----------------
__global__ void zero_detect_kernel(const void* ei) {
    int i = blockIdx.x * blockDim.x + threadIdx.x;
    if (i < NN) g_cnt[i] = 0;
    if (i == 0) {
        const long long* p = (const long long*)ei;
        bool ok = true;
        #pragma unroll
        for (int k = 0; k < 8; k++) {
            long long v = p[k];
            if (v < 0 || v >= NN) ok = false;
        }
        g_is64 = ok ? 1 : 0;
    }
}

// ---------------- CSR build ----------------
__global__ void deg_kernel(const void* __restrict__ ei) {
    int e = blockIdx.x * blockDim.x + threadIdx.x;
    if (e < NE) atomicAdd(&g_cnt[edge_at(ei, (long long)NE + e)], 1);
}

__global__ void __launch_bounds__(256) scan1_kernel() {
    __shared__ int wsum[8];
    const int t = threadIdx.x, b = blockIdx.x;
    const int i = b * 256 + t;
    int v = (i < NN) ? g_cnt[i] + 1 : 0;
    int x = v;
    #pragma unroll
    for (int o = 1; o < 32; o <<= 1) {
        int y = __shfl_up_sync(0xffffffffu, x, o);
        if ((t & 31) >= o) x += y;
    }
    if ((t & 31) == 31) wsum[t >> 5] = x;
    __syncthreads();
    if (t < 8) {
        int w = wsum[t];
        #pragma unroll
        for (int o = 1; o < 8; o <<= 1) {
            int y = __shfl_up_sync(0xffu, w, o);
            if (t >= o) w += y;
        }
        wsum[t] = w;
    }
    __syncthreads();
    int incl = x + ((t >= 32) ? wsum[(t >> 5) - 1] : 0);
    if (i < NN) g_tmp[i] = incl;
    if (t == 255) g_bsum[b] = incl;
}

__global__ void __launch_bounds__(256) scan2_kernel() {
    __shared__ int wsum[8];
    const int t = threadIdx.x;
    int v = (t < NBLK) ? g_bsum[t] : 0;
    int x = v;
    #pragma unroll
    for (int o = 1; o < 32; o <<= 1) {
        int y = __shfl_up_sync(0xffffffffu, x, o);
        if ((t & 31) >= o) x += y;
    }
    if ((t & 31) == 31) wsum[t >> 5] = x;
    __syncthreads();
    if (t < 8) {
        int w = wsum[t];
        #pragma unroll
        for (int o = 1; o < 8; o <<= 1) {
            int y = __shfl_up_sync(0xffu, w, o);
            if (t >= o) w += y;
        }
        wsum[t] = w;
    }
    __syncthreads();
    int incl = x + ((t >= 32) ? wsum[(t >> 5) - 1] : 0);
    if (t < NBLK) g_boff[t] = incl - v;
    if (t == 0) g_rowptr[0] = 0;
}

__global__ void scan3_kernel() {
    int i = blockIdx.x * blockDim.x + threadIdx.x;
    if (i < NN) {
        int rp1 = g_tmp[i] + g_boff[i >> 8];
        g_rowptr[i + 1] = rp1;
        g_cnt[i] = 0;
        g_srcs[rp1 - 1] = i;
    }
}

__global__ void scatter_kernel(const void* __restrict__ ei) {
    int e = blockIdx.x * blockDim.x + threadIdx.x;
    if (e < NE) {
        int s = edge_at(ei, e);
        int d = edge_at(ei, (long long)NE + e);
        int pos = g_rowptr[d] + atomicAdd(&g_cnt[d], 1);
        g_srcs[pos] = s;
    }
}

// ---------------- tf32 tensor-core GEMM with register-prefetch pipeline ----------------
template <bool INTERNAL_SRC>
__global__ void __launch_bounds__(256) gemm_tc_kernel(const float* __restrict__ Aext,
                                                      const float* __restrict__ B, int M) {
    const float* A = INTERNAL_SRC ? g_o1 : Aext;
    float* C = g_h;

    __shared__ uint32_t As[32][129];
    __shared__ uint32_t Bs[32][132];

    const int t    = threadIdx.x;
    const int lane = t & 31;
    const int w    = t >> 5;
    const int wr   = w & 3;
    const int wc   = w >> 2;
    const int tig  = lane & 3;
    const int gid  = lane >> 2;
    const int bm   = blockIdx.x * 128;
    const int bn   = blockIdx.y * 128;

    float acc[2][8][4];
    #pragma unroll
    for (int mt = 0; mt < 2; mt++)
        #pragma unroll
        for (int nt = 0; nt < 8; nt++)
            #pragma unroll
            for (int c = 0; c < 4; c++) acc[mt][nt][c] = 0.f;

    const int a_r  = t >> 3;
    const int a_ko = (t & 7) * 4;

    float4 pa[4], pb[4];

    #pragma unroll
    for (int i = 0; i < 4; i++) {
        int grow = bm + a_r + i * 32;
        pa[i] = (grow < M) ? *(const float4*)(A + (size_t)grow * EMBD + a_ko)
                           : make_float4(0.f, 0.f, 0.f, 0.f);
    }
    #pragma unroll
    for (int i = 0; i < 4; i++) {
        int idx = t + i * 256;
        int kr  = idx >> 5;
        int c4  = (idx & 31) * 4;
        pb[i] = *(const float4*)(B + (size_t)kr * EMBD + bn + c4);
    }

    for (int kc = 0; kc < 8; kc++) {
        #pragma unroll
        for (int i = 0; i < 4; i++) {
            int r = a_r + i * 32;
            As[a_ko + 0][r] = f2tf(pa[i].x);
            As[a_ko + 1][r] = f2tf(pa[i].y);
            As[a_ko + 2][r] = f2tf(pa[i].z);
            As[a_ko + 3][r] = f2tf(pa[i].w);
        }
        #pragma unroll
        for (int i = 0; i < 4; i++) {
            int idx = t + i * 256;
            int kr  = idx >> 5;
            int c4  = (idx & 31) * 4;
            uint4 u;
            u.x = f2tf(pb[i].x); u.y = f2tf(pb[i].y); u.z = f2tf(pb[i].z); u.w = f2tf(pb[i].w);
            *(uint4*)&Bs[kr][c4] = u;
        }
        __syncthreads();

        if (kc + 1 < 8) {
            const int kbase = (kc + 1) * 32;
            #pragma unroll
            for (int i = 0; i < 4; i++) {
                int grow = bm + a_r + i * 32;
                pa[i] = (grow < M) ? *(const float4*)(A + (size_t)grow * EMBD + kbase + a_ko)
                                   : make_float4(0.f, 0.f, 0.f, 0.f);
            }
            #pragma unroll
            for (int i = 0; i < 4; i++) {
                int idx = t + i * 256;
                int kr  = idx >> 5;
                int c4  = (idx & 31) * 4;
                pb[i] = *(const float4*)(B + (size_t)(kbase + kr) * EMBD + bn + c4);
            }
        }

        #pragma unroll
        for (int k0 = 0; k0 < 32; k0 += 8) {
            uint32_t af[2][4], bf[8][2];
            const int kr0 = k0 + tig, kr1 = k0 + tig + 4;
            #pragma unroll
            for (int mt = 0; mt < 2; mt++) {
                int m0 = wr * 32 + mt * 16 + gid;
                af[mt][0] = As[kr0][m0];
                af[mt][1] = As[kr0][m0 + 8];
                af[mt][2] = As[kr1][m0];
                af[mt][3] = As[kr1][m0 + 8];
            }
            #pragma unroll
            for (int nt = 0; nt < 8; nt++) {
                int n0 = wc * 64 + nt * 8 + gid;
                bf[nt][0] = Bs[kr0][n0];
                bf[nt][1] = Bs[kr1][n0];
            }
            #pragma unroll
            for (int mt = 0; mt < 2; mt++)
                #pragma unroll
                for (int nt = 0; nt < 8; nt++) {
                    asm volatile(
                        "mma.sync.aligned.m16n8k8.row.col.f32.tf32.tf32.f32 "
                        "{%0,%1,%2,%3}, {%4,%5,%6,%7}, {%8,%9}, {%0,%1,%2,%3};\n"
                        : "+f"(acc[mt][nt][0]), "+f"(acc[mt][nt][1]),
                          "+f"(acc[mt][nt][2]), "+f"(acc[mt][nt][3])
                        : "r"(af[mt][0]), "r"(af[mt][1]), "r"(af[mt][2]), "r"(af[mt][3]),
                          "r"(bf[nt][0]), "r"(bf[nt][1]));
                }
        }
        __syncthreads();
    }

    #pragma unroll
    for (int mt = 0; mt < 2; mt++) {
        int row0 = bm + wr * 32 + mt * 16 + gid;
        #pragma unroll
        for (int nt = 0; nt < 8; nt++) {
            int col = bn + wc * 64 + nt * 8 + tig * 2;
            if (row0 < M)
                *(float2*)(C + (size_t)row0 * EMBD + col) = make_float2(acc[mt][nt][0], acc[mt][nt][1]);
            if (row0 + 8 < M)
                *(float2*)(C + (size_t)(row0 + 8) * EMBD + col) = make_float2(acc[mt][nt][2], acc[mt][nt][3]);
        }
    }
}

// ---------------- per-node attention logits (warp per node, 8 nodes/block) ----------------
template <int H>
__global__ void __launch_bounds__(256) al_kernel(const float* __restrict__ asrc,
                                                 const float* __restrict__ adst) {
    const int t = threadIdx.x;
    const int lane = t & 31;
    const int n = blockIdx.x * 8 + (t >> 5);
    if (n >= NN) return;

    const float* row = g_h + (size_t)n * EMBD + lane * 8;
    float4 v0 = *(const float4*)(row);
    float4 v1 = *(const float4*)(row + 4);
    const float* as = asrc + lane * 8;
    const float* ad = adst + lane * 8;
    float4 s0 = *(const float4*)(as);
    float4 s1 = *(const float4*)(as + 4);
    float4 d0 = *(const float4*)(ad);
    float4 d1 = *(const float4*)(ad + 4);

    float ps = v0.x*s0.x + v0.y*s0.y + v0.z*s0.z + v0.w*s0.w
             + v1.x*s1.x + v1.y*s1.y + v1.z*s1.z + v1.w*s1.w;
    float pd = v0.x*d0.x + v0.y*d0.y + v0.z*d0.z + v0.w*d0.w
             + v1.x*d1.x + v1.y*d1.y + v1.z*d1.z + v1.w*d1.w;

    if (H == 8) {
        #pragma unroll
        for (int o = 1; o < 4; o <<= 1) {
            ps += __shfl_xor_sync(0xffffffffu, ps, o);
            pd += __shfl_xor_sync(0xffffffffu, pd, o);
        }
        if ((lane & 3) == 0) {
            g_als[n * 8 + (lane >> 2)] = ps;
            g_ald[n * 8 + (lane >> 2)] = pd;
        }
    } else {
        #pragma unroll
        for (int o = 16; o; o >>= 1) {
            ps += __shfl_xor_sync(0xffffffffu, ps, o);
            pd += __shfl_xor_sync(0xffffffffu, pd, o);
        }
        if (lane == 0) { g_als[n] = ps; g_ald[n] = pd; }
    }
}

// ---------------- FUSED alpha + aggregation ----------------
// 4 edge-groups x 64 threads; alpha staged per 64-edge chunk in smem;
// z accumulated inline; normalization + bias in epilogue.
template <int H, bool INTERNAL_DST>
__global__ void __launch_bounds__(256) agg_kernel(const float* __restrict__ bias,
                                                  float* __restrict__ outext) {
    const int d = blockIdx.x, t = threadIdx.x;
    const int g  = t >> 6;            // edge group 0..3
    const int t4 = t & 63;            // lane within group
    const int c0 = t4 * 4;            // base column (0..252)
    const int hh = (H == 8) ? (c0 >> 5) : 0;
    const int begin = g_rowptr[d], end = g_rowptr[d + 1];

    __shared__ int   s_src[64];
    __shared__ float s_alpha[64 * H];
    __shared__ float s_red[4][256];
    __shared__ float s_z[4][H];

    float4 acc = make_float4(0.f, 0.f, 0.f, 0.f);
    float z = 0.f;

    for (int c = begin; c < end; c += 64) {
        int len = min(64, end - c);
        __syncthreads();                       // protect smem reuse across chunks
        if (t < len) s_src[t] = g_srcs[c + t];
        __syncthreads();
        // stage unnormalized alphas for this chunk (len*H values, ≤512)
        for (int idx = t; idx < len * H; idx += 256) {
            int j = (H == 8) ? (idx >> 3) : idx;
            int h = (H == 8) ? (idx & 7) : 0;
            s_alpha[idx] = __expf(lrelu(__ldg(&g_als[s_src[j] * H + h]) + g_ald[d * H + h]));
        }
        __syncthreads();
        // gather: group g handles edges j = g, g+4, ...
        for (int j = g; j < len; j += 4) {
            float a = s_alpha[j * H + hh];
            z += a;
            const float4 hv = *(const float4*)(g_h + (size_t)s_src[j] * EMBD + c0);
            acc.x += a * hv.x; acc.y += a * hv.y; acc.z += a * hv.z; acc.w += a * hv.w;
        }
    }

    // cross-group reduction
    *(float4*)&s_red[g][c0] = acc;
    if (H == 8) { if ((t4 & 7) == 0) s_z[g][t4 >> 3] = z; }
    else        { if (t4 == 0)       s_z[g][0] = z; }
    __syncthreads();

    const int myh = (H == 8) ? (t >> 5) : 0;
    float zt = s_z[0][myh] + s_z[1][myh] + s_z[2][myh] + s_z[3][myh];
    float av = s_red[0][t] + s_red[1][t] + s_red[2][t] + s_red[3][t];
    float r = av / (zt + 1e-16f) + bias[t];
    if (INTERNAL_DST) g_o1[(size_t)d * EMBD + t] = r;
    else              outext[(size_t)d * EMBD + t] = r;
}

// ---------------- launch ----------------
extern "C" void kernel_launch(void* const* d_in, const int* in_sizes, int n_in,
                              void* d_out, int out_size) {
    const float* x   = (const float*)d_in[0];
    const void*  ei  = d_in[1];
    const float* W1  = (const float*)d_in[2];
    const float* as1 = (const float*)d_in[3];
    const float* ad1 = (const float*)d_in[4];
    const float* b1  = (const float*)d_in[5];
    const float* W2  = (const float*)d_in[6];
    const float* as2 = (const float*)d_in[7];
    const float* ad2 = (const float*)d_in[8];
    const float* b2  = (const float*)d_in[9];
    float* out = (float*)d_out;

    zero_detect_kernel<<<NBLK, 256>>>(ei);
    deg_kernel<<<(NE + 255) / 256, 256>>>(ei);
    scan1_kernel<<<NBLK, 256>>>();
    scan2_kernel<<<1, 256>>>();
    scan3_kernel<<<NBLK, 256>>>();
    scatter_kernel<<<(NE + 255) / 256, 256>>>(ei);

    dim3 gg((NN + 127) / 128, 2);
    const int ALB = (NN + 7) / 8;

    // layer 1 (H=8, F=32)
    gemm_tc_kernel<false><<<gg, 256>>>(x, W1, NN);
    al_kernel<8><<<ALB, 256>>>(as1, ad1);
    agg_kernel<8, true><<<NN, 256>>>(b1, nullptr);

    // layer 2 (H=1, F=256)
    gemm_tc_kernel<true><<<gg, 256>>>(nullptr, W2, NN);
    al_kernel<1><<<ALB, 256>>>(as2, ad2);
    agg_kernel<1, false><<<NN, 256>>>(b2, out);
}

// round 10
// speedup vs baseline: 1.9731x; 1.2091x over previous
#include <cuda_runtime.h>
#include <cstdint>

#define NN   50000
#define EMBD 256
#define NE   800000
#define ETOT (NE + NN)
#define NBLK 196                      // ceil(NN/256)

// ---------------- static device scratch ----------------
__device__ float g_h[(size_t)NN * EMBD];
__device__ float g_o1[(size_t)NN * EMBD];
__device__ float g_als[NN * 8];
__device__ float g_ald[NN * 8];
__device__ int   g_rowptr[NN + 1];
__device__ int   g_cnt[NN];
__device__ int   g_srcs[ETOT];
__device__ int   g_tmp[NN];
__device__ int   g_bsum[NBLK];
__device__ int   g_boff[NBLK];
__device__ int   g_is64;

__device__ __forceinline__ float lrelu(float x) { return x > 0.f ? x : 0.2f * x; }

__device__ __forceinline__ int edge_at(const void* ei, long long idx) {
    if (g_is64) return (int)((const long long*)ei)[idx];
    return ((const int*)ei)[idx];
}

__device__ __forceinline__ uint32_t f2tf(float f) {
    uint32_t u;
    asm("cvt.rna.tf32.f32 %0, %1;" : "=r"(u) : "f"(f));
    return u;
}

__device__ __forceinline__ void gbar(int id) {
    asm volatile("bar.sync %0, 64;" :: "r"(id) : "memory");
}

// ---------------- zero counters + dtype probe (merged) ----------------
__global__ void zero_detect_kernel(const void* ei) {
    int i = blockIdx.x * blockDim.x + threadIdx.x;
    if (i < NN) g_cnt[i] = 0;
    if (i == 0) {
        const long long* p = (const long long*)ei;
        bool ok = true;
        #pragma unroll
        for (int k = 0; k < 8; k++) {
            long long v = p[k];
            if (v < 0 || v >= NN) ok = false;
        }
        g_is64 = ok ? 1 : 0;
    }
}

// ---------------- CSR build ----------------
__global__ void deg_kernel(const void* __restrict__ ei) {
    int e = blockIdx.x * blockDim.x + threadIdx.x;
    if (e < NE) atomicAdd(&g_cnt[edge_at(ei, (long long)NE + e)], 1);
}

__global__ void __launch_bounds__(256) scan1_kernel() {
    __shared__ int wsum[8];
    const int t = threadIdx.x, b = blockIdx.x;
    const int i = b * 256 + t;
    int v = (i < NN) ? g_cnt[i] + 1 : 0;
    int x = v;
    #pragma unroll
    for (int o = 1; o < 32; o <<= 1) {
        int y = __shfl_up_sync(0xffffffffu, x, o);
        if ((t & 31) >= o) x += y;
    }
    if ((t & 31) == 31) wsum[t >> 5] = x;
    __syncthreads();
    if (t < 8) {
        int w = wsum[t];
        #pragma unroll
        for (int o = 1; o < 8; o <<= 1) {
            int y = __shfl_up_sync(0xffu, w, o);
            if (t >= o) w += y;
        }
        wsum[t] = w;
    }
    __syncthreads();
    int incl = x + ((t >= 32) ? wsum[(t >> 5) - 1] : 0);
    if (i < NN) g_tmp[i] = incl;
    if (t == 255) g_bsum[b] = incl;
}

__global__ void __launch_bounds__(256) scan2_kernel() {
    __shared__ int wsum[8];
    const int t = threadIdx.x;
    int v = (t < NBLK) ? g_bsum[t] : 0;
    int x = v;
    #pragma unroll
    for (int o = 1; o < 32; o <<= 1) {
        int y = __shfl_up_sync(0xffffffffu, x, o);
        if ((t & 31) >= o) x += y;
    }
    if ((t & 31) == 31) wsum[t >> 5] = x;
    __syncthreads();
    if (t < 8) {
        int w = wsum[t];
        #pragma unroll
        for (int o = 1; o < 8; o <<= 1) {
            int y = __shfl_up_sync(0xffu, w, o);
            if (t >= o) w += y;
        }
        wsum[t] = w;
    }
    __syncthreads();
    int incl = x + ((t >= 32) ? wsum[(t >> 5) - 1] : 0);
    if (t < NBLK) g_boff[t] = incl - v;
    if (t == 0) g_rowptr[0] = 0;
}

__global__ void scan3_kernel() {
    int i = blockIdx.x * blockDim.x + threadIdx.x;
    if (i < NN) {
        int rp1 = g_tmp[i] + g_boff[i >> 8];
        g_rowptr[i + 1] = rp1;
        g_cnt[i] = 0;
        g_srcs[rp1 - 1] = i;
    }
}

__global__ void scatter_kernel(const void* __restrict__ ei) {
    int e = blockIdx.x * blockDim.x + threadIdx.x;
    if (e < NE) {
        int s = edge_at(ei, e);
        int d = edge_at(ei, (long long)NE + e);
        int pos = g_rowptr[d] + atomicAdd(&g_cnt[d], 1);
        g_srcs[pos] = s;
    }
}

// ---------------- tf32 tensor-core GEMM with register-prefetch pipeline ----------------
template <bool INTERNAL_SRC>
__global__ void __launch_bounds__(256) gemm_tc_kernel(const float* __restrict__ Aext,
                                                      const float* __restrict__ B, int M) {
    const float* A = INTERNAL_SRC ? g_o1 : Aext;
    float* C = g_h;

    __shared__ uint32_t As[32][129];
    __shared__ uint32_t Bs[32][132];

    const int t    = threadIdx.x;
    const int lane = t & 31;
    const int w    = t >> 5;
    const int wr   = w & 3;
    const int wc   = w >> 2;
    const int tig  = lane & 3;
    const int gid  = lane >> 2;
    const int bm   = blockIdx.x * 128;
    const int bn   = blockIdx.y * 128;

    float acc[2][8][4];
    #pragma unroll
    for (int mt = 0; mt < 2; mt++)
        #pragma unroll
        for (int nt = 0; nt < 8; nt++)
            #pragma unroll
            for (int c = 0; c < 4; c++) acc[mt][nt][c] = 0.f;

    const int a_r  = t >> 3;
    const int a_ko = (t & 7) * 4;

    float4 pa[4], pb[4];

    #pragma unroll
    for (int i = 0; i < 4; i++) {
        int grow = bm + a_r + i * 32;
        pa[i] = (grow < M) ? *(const float4*)(A + (size_t)grow * EMBD + a_ko)
                           : make_float4(0.f, 0.f, 0.f, 0.f);
    }
    #pragma unroll
    for (int i = 0; i < 4; i++) {
        int idx = t + i * 256;
        int kr  = idx >> 5;
        int c4  = (idx & 31) * 4;
        pb[i] = *(const float4*)(B + (size_t)kr * EMBD + bn + c4);
    }

    for (int kc = 0; kc < 8; kc++) {
        #pragma unroll
        for (int i = 0; i < 4; i++) {
            int r = a_r + i * 32;
            As[a_ko + 0][r] = f2tf(pa[i].x);
            As[a_ko + 1][r] = f2tf(pa[i].y);
            As[a_ko + 2][r] = f2tf(pa[i].z);
            As[a_ko + 3][r] = f2tf(pa[i].w);
        }
        #pragma unroll
        for (int i = 0; i < 4; i++) {
            int idx = t + i * 256;
            int kr  = idx >> 5;
            int c4  = (idx & 31) * 4;
            uint4 u;
            u.x = f2tf(pb[i].x); u.y = f2tf(pb[i].y); u.z = f2tf(pb[i].z); u.w = f2tf(pb[i].w);
            *(uint4*)&Bs[kr][c4] = u;
        }
        __syncthreads();

        if (kc + 1 < 8) {
            const int kbase = (kc + 1) * 32;
            #pragma unroll
            for (int i = 0; i < 4; i++) {
                int grow = bm + a_r + i * 32;
                pa[i] = (grow < M) ? *(const float4*)(A + (size_t)grow * EMBD + kbase + a_ko)
                                   : make_float4(0.f, 0.f, 0.f, 0.f);
            }
            #pragma unroll
            for (int i = 0; i < 4; i++) {
                int idx = t + i * 256;
                int kr  = idx >> 5;
                int c4  = (idx & 31) * 4;
                pb[i] = *(const float4*)(B + (size_t)(kbase + kr) * EMBD + bn + c4);
            }
        }

        #pragma unroll
        for (int k0 = 0; k0 < 32; k0 += 8) {
            uint32_t af[2][4], bf[8][2];
            const int kr0 = k0 + tig, kr1 = k0 + tig + 4;
            #pragma unroll
            for (int mt = 0; mt < 2; mt++) {
                int m0 = wr * 32 + mt * 16 + gid;
                af[mt][0] = As[kr0][m0];
                af[mt][1] = As[kr0][m0 + 8];
                af[mt][2] = As[kr1][m0];
                af[mt][3] = As[kr1][m0 + 8];
            }
            #pragma unroll
            for (int nt = 0; nt < 8; nt++) {
                int n0 = wc * 64 + nt * 8 + gid;
                bf[nt][0] = Bs[kr0][n0];
                bf[nt][1] = Bs[kr1][n0];
            }
            #pragma unroll
            for (int mt = 0; mt < 2; mt++)
                #pragma unroll
                for (int nt = 0; nt < 8; nt++) {
                    asm volatile(
                        "mma.sync.aligned.m16n8k8.row.col.f32.tf32.tf32.f32 "
                        "{%0,%1,%2,%3}, {%4,%5,%6,%7}, {%8,%9}, {%0,%1,%2,%3};\n"
                        : "+f"(acc[mt][nt][0]), "+f"(acc[mt][nt][1]),
                          "+f"(acc[mt][nt][2]), "+f"(acc[mt][nt][3])
                        : "r"(af[mt][0]), "r"(af[mt][1]), "r"(af[mt][2]), "r"(af[mt][3]),
                          "r"(bf[nt][0]), "r"(bf[nt][1]));
                }
        }
        __syncthreads();
    }

    #pragma unroll
    for (int mt = 0; mt < 2; mt++) {
        int row0 = bm + wr * 32 + mt * 16 + gid;
        #pragma unroll
        for (int nt = 0; nt < 8; nt++) {
            int col = bn + wc * 64 + nt * 8 + tig * 2;
            if (row0 < M)
                *(float2*)(C + (size_t)row0 * EMBD + col) = make_float2(acc[mt][nt][0], acc[mt][nt][1]);
            if (row0 + 8 < M)
                *(float2*)(C + (size_t)(row0 + 8) * EMBD + col) = make_float2(acc[mt][nt][2], acc[mt][nt][3]);
        }
    }
}

// ---------------- per-node attention logits (warp per node, 8 nodes/block) ----------------
template <int H>
__global__ void __launch_bounds__(256) al_kernel(const float* __restrict__ asrc,
                                                 const float* __restrict__ adst) {
    const int t = threadIdx.x;
    const int lane = t & 31;
    const int n = blockIdx.x * 8 + (t >> 5);
    if (n >= NN) return;

    const float* row = g_h + (size_t)n * EMBD + lane * 8;
    float4 v0 = *(const float4*)(row);
    float4 v1 = *(const float4*)(row + 4);
    const float* as = asrc + lane * 8;
    const float* ad = adst + lane * 8;
    float4 s0 = *(const float4*)(as);
    float4 s1 = *(const float4*)(as + 4);
    float4 d0 = *(const float4*)(ad);
    float4 d1 = *(const float4*)(ad + 4);

    float ps = v0.x*s0.x + v0.y*s0.y + v0.z*s0.z + v0.w*s0.w
             + v1.x*s1.x + v1.y*s1.y + v1.z*s1.z + v1.w*s1.w;
    float pd = v0.x*d0.x + v0.y*d0.y + v0.z*d0.z + v0.w*d0.w
             + v1.x*d1.x + v1.y*d1.y + v1.z*d1.z + v1.w*d1.w;

    if (H == 8) {
        #pragma unroll
        for (int o = 1; o < 4; o <<= 1) {
            ps += __shfl_xor_sync(0xffffffffu, ps, o);
            pd += __shfl_xor_sync(0xffffffffu, pd, o);
        }
        if ((lane & 3) == 0) {
            g_als[n * 8 + (lane >> 2)] = ps;
            g_ald[n * 8 + (lane >> 2)] = pd;
        }
    } else {
        #pragma unroll
        for (int o = 16; o; o >>= 1) {
            ps += __shfl_xor_sync(0xffffffffu, ps, o);
            pd += __shfl_xor_sync(0xffffffffu, pd, o);
        }
        if (lane == 0) { g_als[n] = ps; g_ald[n] = pd; }
    }
}

// ---------------- FUSED alpha + aggregation: 4 nodes/block, 64-thread groups ----------------
// Each group owns one node: walks all its edges (64 threads x float4 = full row),
// z accumulated per-thread for free (same alphas), no cross-group reduction.
template <int H, bool INTERNAL_DST>
__global__ void __launch_bounds__(256) agg_kernel(const float* __restrict__ bias,
                                                  float* __restrict__ outext) {
    const int t  = threadIdx.x;
    const int g  = t >> 6;            // group 0..3 -> node
    const int t4 = t & 63;
    const int c0 = t4 * 4;            // column base 0..252
    const int hh = (H == 8) ? (c0 >> 5) : 0;
    const int d  = blockIdx.x * 4 + g;   // NN % 4 == 0, always valid

    __shared__ int   s_src[4][64];
    __shared__ float s_alpha[4][64 * H];

    const int begin = g_rowptr[d], end = g_rowptr[d + 1];
    const float aldv = g_ald[d * H + ((H == 8) ? (t4 & 7) : 0)];  // head for staging below

    float4 acc = make_float4(0.f, 0.f, 0.f, 0.f);
    float z = 0.f;

    for (int c = begin; c < end; c += 64) {
        int len = min(64, end - c);
        gbar(1 + g);
        if (t4 < len) s_src[g][t4] = g_srcs[c + t4];
        gbar(1 + g);
        // stage unnormalized alphas: len*H values over 64 threads
        if (H == 8) {
            for (int idx = t4; idx < len * 8; idx += 64) {
                int j = idx >> 3, h = idx & 7;
                // aldv holds head (t4&7)'s value; idx stride 64 keeps h == t4&7
                s_alpha[g][idx] = __expf(lrelu(__ldg(&g_als[s_src[g][j] * 8 + h]) + aldv));
            }
        } else {
            for (int idx = t4; idx < len; idx += 64)
                s_alpha[g][idx] = __expf(lrelu(__ldg(&g_als[s_src[g][idx]]) + aldv));
        }
        gbar(1 + g);
        for (int j = 0; j < len; j++) {
            float a = s_alpha[g][j * H + hh];
            z += a;
            const float4 hv = *(const float4*)(g_h + (size_t)s_src[g][j] * EMBD + c0);
            acc.x += a * hv.x; acc.y += a * hv.y; acc.z += a * hv.z; acc.w += a * hv.w;
        }
    }

    const float inv = 1.f / (z + 1e-16f);
    const float4 bv = *(const float4*)(bias + c0);
    float4 r = make_float4(acc.x * inv + bv.x, acc.y * inv + bv.y,
                           acc.z * inv + bv.z, acc.w * inv + bv.w);
    float* dst = INTERNAL_DST ? (g_o1 + (size_t)d * EMBD + c0)
                              : (outext + (size_t)d * EMBD + c0);
    *(float4*)dst = r;
}

// ---------------- launch ----------------
extern "C" void kernel_launch(void* const* d_in, const int* in_sizes, int n_in,
                              void* d_out, int out_size) {
    const float* x   = (const float*)d_in[0];
    const void*  ei  = d_in[1];
    const float* W1  = (const float*)d_in[2];
    const float* as1 = (const float*)d_in[3];
    const float* ad1 = (const float*)d_in[4];
    const float* b1  = (const float*)d_in[5];
    const float* W2  = (const float*)d_in[6];
    const float* as2 = (const float*)d_in[7];
    const float* ad2 = (const float*)d_in[8];
    const float* b2  = (const float*)d_in[9];
    float* out = (float*)d_out;

    zero_detect_kernel<<<NBLK, 256>>>(ei);
    deg_kernel<<<(NE + 255) / 256, 256>>>(ei);
    scan1_kernel<<<NBLK, 256>>>();
    scan2_kernel<<<1, 256>>>();
    scan3_kernel<<<NBLK, 256>>>();
    scatter_kernel<<<(NE + 255) / 256, 256>>>(ei);

    dim3 gg((NN + 127) / 128, 2);
    const int ALB = (NN + 7) / 8;
    const int AGB = NN / 4;

    // layer 1 (H=8, F=32)
    gemm_tc_kernel<false><<<gg, 256>>>(x, W1, NN);
    al_kernel<8><<<ALB, 256>>>(as1, ad1);
    agg_kernel<8, true><<<AGB, 256>>>(b1, nullptr);

    // layer 2 (H=1, F=256)
    gemm_tc_kernel<true><<<gg, 256>>>(nullptr, W2, NN);
    al_kernel<1><<<ALB, 256>>>(as2, ad2);
    agg_kernel<1, false><<<AGB, 256>>>(b2, out);
}

// round 11
// speedup vs baseline: 2.0002x; 1.0137x over previous
#include <cuda_runtime.h>
#include <cstdint>

#define NN   50000
#define EMBD 256
#define NE   800000
#define ETOT (NE + NN)
#define NBLK 196                      // ceil(NN/256)

// ---------------- static device scratch ----------------
__device__ float g_h[(size_t)NN * EMBD];
__device__ float g_o1[(size_t)NN * EMBD];
__device__ float g_als[NN * 8];       // layer-1 (H=8) logit pieces
__device__ float g_ald[NN * 8];
__device__ float g_als2[NN];          // layer-2 (H=1)
__device__ float g_ald2[NN];
__device__ int   g_rowptr[NN + 1];
__device__ int   g_cnt[NN];
__device__ int   g_srcs[ETOT];
__device__ int   g_tmp[NN];
__device__ int   g_bsum[NBLK];
__device__ int   g_is64;

__device__ __forceinline__ float lrelu(float x) { return x > 0.f ? x : 0.2f * x; }

__device__ __forceinline__ uint32_t f2tf(float f) {
    uint32_t u;
    asm("cvt.rna.tf32.f32 %0, %1;" : "=r"(u) : "f"(f));
    return u;
}

__device__ __forceinline__ void gbar(int id) {
    asm volatile("bar.sync %0, 64;" :: "r"(id) : "memory");
}

// ---------------- init: zero counters + logit accumulators + dtype probe ----------------
__global__ void init_kernel(const void* ei) {
    const int i = blockIdx.x * blockDim.x + threadIdx.x;
    const int stride = gridDim.x * blockDim.x;
    if (i < NN) { g_cnt[i] = 0; g_als2[i] = 0.f; g_ald2[i] = 0.f; }
    for (int j = i; j < NN * 8; j += stride) { g_als[j] = 0.f; g_ald[j] = 0.f; }
    if (i == 0) {
        const long long* p = (const long long*)ei;
        bool ok = true;
        #pragma unroll
        for (int k = 0; k < 8; k++) {
            long long v = p[k];
            if (v < 0 || v >= NN) ok = false;
        }
        g_is64 = ok ? 1 : 0;
    }
}

// ---------------- CSR build (4 edges / thread) ----------------
__global__ void deg_kernel(const void* __restrict__ ei) {
    int e4 = blockIdx.x * blockDim.x + threadIdx.x;
    if (e4 >= NE / 4) return;
    if (!g_is64) {
        int4 d = ((const int4*)((const int*)ei + NE))[e4];
        atomicAdd(&g_cnt[d.x], 1);
        atomicAdd(&g_cnt[d.y], 1);
        atomicAdd(&g_cnt[d.z], 1);
        atomicAdd(&g_cnt[d.w], 1);
    } else {
        const long long* p = (const long long*)ei + NE;
        #pragma unroll
        for (int k = 0; k < 4; k++) atomicAdd(&g_cnt[(int)p[e4 * 4 + k]], 1);
    }
}

__global__ void __launch_bounds__(256) scan1_kernel() {
    __shared__ int wsum[8];
    const int t = threadIdx.x, b = blockIdx.x;
    const int i = b * 256 + t;
    int v = (i < NN) ? g_cnt[i] + 1 : 0;
    int x = v;
    #pragma unroll
    for (int o = 1; o < 32; o <<= 1) {
        int y = __shfl_up_sync(0xffffffffu, x, o);
        if ((t & 31) >= o) x += y;
    }
    if ((t & 31) == 31) wsum[t >> 5] = x;
    __syncthreads();
    if (t < 8) {
        int w = wsum[t];
        #pragma unroll
        for (int o = 1; o < 8; o <<= 1) {
            int y = __shfl_up_sync(0xffu, w, o);
            if (t >= o) w += y;
        }
        wsum[t] = w;
    }
    __syncthreads();
    int incl = x + ((t >= 32) ? wsum[(t >> 5) - 1] : 0);
    if (i < NN) g_tmp[i] = incl;
    if (t == 255) g_bsum[b] = incl;
}

// merged scan2+scan3: each block computes its own exclusive block-offset
__global__ void __launch_bounds__(256) scan_apply_kernel() {
    __shared__ int red[8];
    __shared__ int s_off;
    const int t = threadIdx.x, b = blockIdx.x;
    int v = (t < b) ? g_bsum[t] : 0;     // NBLK=196 < 256
    #pragma unroll
    for (int o = 16; o; o >>= 1) v += __shfl_xor_sync(0xffffffffu, v, o);
    if ((t & 31) == 0) red[t >> 5] = v;
    __syncthreads();
    if (t == 0) {
        int s = 0;
        #pragma unroll
        for (int ww = 0; ww < 8; ww++) s += red[ww];
        s_off = s;
        if (b == 0) g_rowptr[0] = 0;
    }
    __syncthreads();
    const int i = b * 256 + t;
    if (i < NN) {
        int rp1 = g_tmp[i] + s_off;
        g_rowptr[i + 1] = rp1;
        g_cnt[i] = 0;
        g_srcs[rp1 - 1] = i;
    }
}

__global__ void scatter_kernel(const void* __restrict__ ei) {
    int e4 = blockIdx.x * blockDim.x + threadIdx.x;
    if (e4 >= NE / 4) return;
    int s[4], d[4];
    if (!g_is64) {
        int4 sv = ((const int4*)ei)[e4];
        int4 dv = ((const int4*)((const int*)ei + NE))[e4];
        s[0] = sv.x; s[1] = sv.y; s[2] = sv.z; s[3] = sv.w;
        d[0] = dv.x; d[1] = dv.y; d[2] = dv.z; d[3] = dv.w;
    } else {
        const long long* ps = (const long long*)ei;
        const long long* pd = ps + NE;
        #pragma unroll
        for (int k = 0; k < 4; k++) { s[k] = (int)ps[e4 * 4 + k]; d[k] = (int)pd[e4 * 4 + k]; }
    }
    #pragma unroll
    for (int k = 0; k < 4; k++) {
        int pos = g_rowptr[d[k]] + atomicAdd(&g_cnt[d[k]], 1);
        g_srcs[pos] = s[k];
    }
}

// ---------------- tf32 GEMM + fused al epilogue ----------------
// H selects the logit buffers (8 -> g_als/g_ald, 1 -> g_als2/g_ald2).
template <int H, bool INTERNAL_SRC>
__global__ void __launch_bounds__(256) gemm_tc_kernel(const float* __restrict__ Aext,
                                                      const float* __restrict__ B,
                                                      const float* __restrict__ asrc,
                                                      const float* __restrict__ adst, int M) {
    const float* A = INTERNAL_SRC ? g_o1 : Aext;
    float* C = g_h;
    float* ALS = (H == 8) ? g_als : g_als2;
    float* ALD = (H == 8) ? g_ald : g_ald2;

    __shared__ uint32_t As[32][129];
    __shared__ uint32_t Bs[32][132];

    const int t    = threadIdx.x;
    const int lane = t & 31;
    const int w    = t >> 5;
    const int wr   = w & 3;
    const int wc   = w >> 2;
    const int tig  = lane & 3;
    const int gid  = lane >> 2;
    const int bm   = blockIdx.x * 128;
    const int bn   = blockIdx.y * 128;

    float acc[2][8][4];
    #pragma unroll
    for (int mt = 0; mt < 2; mt++)
        #pragma unroll
        for (int nt = 0; nt < 8; nt++)
            #pragma unroll
            for (int c = 0; c < 4; c++) acc[mt][nt][c] = 0.f;

    const int a_r  = t >> 3;
    const int a_ko = (t & 7) * 4;

    float4 pa[4], pb[4];

    #pragma unroll
    for (int i = 0; i < 4; i++) {
        int grow = bm + a_r + i * 32;
        pa[i] = (grow < M) ? *(const float4*)(A + (size_t)grow * EMBD + a_ko)
                           : make_float4(0.f, 0.f, 0.f, 0.f);
    }
    #pragma unroll
    for (int i = 0; i < 4; i++) {
        int idx = t + i * 256;
        int kr  = idx >> 5;
        int c4  = (idx & 31) * 4;
        pb[i] = *(const float4*)(B + (size_t)kr * EMBD + bn + c4);
    }

    for (int kc = 0; kc < 8; kc++) {
        #pragma unroll
        for (int i = 0; i < 4; i++) {
            int r = a_r + i * 32;
            As[a_ko + 0][r] = f2tf(pa[i].x);
            As[a_ko + 1][r] = f2tf(pa[i].y);
            As[a_ko + 2][r] = f2tf(pa[i].z);
            As[a_ko + 3][r] = f2tf(pa[i].w);
        }
        #pragma unroll
        for (int i = 0; i < 4; i++) {
            int idx = t + i * 256;
            int kr  = idx >> 5;
            int c4  = (idx & 31) * 4;
            uint4 u;
            u.x = f2tf(pb[i].x); u.y = f2tf(pb[i].y); u.z = f2tf(pb[i].z); u.w = f2tf(pb[i].w);
            *(uint4*)&Bs[kr][c4] = u;
        }
        __syncthreads();

        if (kc + 1 < 8) {
            const int kbase = (kc + 1) * 32;
            #pragma unroll
            for (int i = 0; i < 4; i++) {
                int grow = bm + a_r + i * 32;
                pa[i] = (grow < M) ? *(const float4*)(A + (size_t)grow * EMBD + kbase + a_ko)
                                   : make_float4(0.f, 0.f, 0.f, 0.f);
            }
            #pragma unroll
            for (int i = 0; i < 4; i++) {
                int idx = t + i * 256;
                int kr  = idx >> 5;
                int c4  = (idx & 31) * 4;
                pb[i] = *(const float4*)(B + (size_t)(kbase + kr) * EMBD + bn + c4);
            }
        }

        #pragma unroll
        for (int k0 = 0; k0 < 32; k0 += 8) {
            uint32_t af[2][4], bf[8][2];
            const int kr0 = k0 + tig, kr1 = k0 + tig + 4;
            #pragma unroll
            for (int mt = 0; mt < 2; mt++) {
                int m0 = wr * 32 + mt * 16 + gid;
                af[mt][0] = As[kr0][m0];
                af[mt][1] = As[kr0][m0 + 8];
                af[mt][2] = As[kr1][m0];
                af[mt][3] = As[kr1][m0 + 8];
            }
            #pragma unroll
            for (int nt = 0; nt < 8; nt++) {
                int n0 = wc * 64 + nt * 8 + gid;
                bf[nt][0] = Bs[kr0][n0];
                bf[nt][1] = Bs[kr1][n0];
            }
            #pragma unroll
            for (int mt = 0; mt < 2; mt++)
                #pragma unroll
                for (int nt = 0; nt < 8; nt++) {
                    asm volatile(
                        "mma.sync.aligned.m16n8k8.row.col.f32.tf32.tf32.f32 "
                        "{%0,%1,%2,%3}, {%4,%5,%6,%7}, {%8,%9}, {%0,%1,%2,%3};\n"
                        : "+f"(acc[mt][nt][0]), "+f"(acc[mt][nt][1]),
                          "+f"(acc[mt][nt][2]), "+f"(acc[mt][nt][3])
                        : "r"(af[mt][0]), "r"(af[mt][1]), "r"(af[mt][2]), "r"(af[mt][3]),
                          "r"(bf[nt][0]), "r"(bf[nt][1]));
                }
        }
        __syncthreads();
    }

    // store C
    #pragma unroll
    for (int mt = 0; mt < 2; mt++) {
        int row0 = bm + wr * 32 + mt * 16 + gid;
        #pragma unroll
        for (int nt = 0; nt < 8; nt++) {
            int col = bn + wc * 64 + nt * 8 + tig * 2;
            if (row0 < M)
                *(float2*)(C + (size_t)row0 * EMBD + col) = make_float2(acc[mt][nt][0], acc[mt][nt][1]);
            if (row0 + 8 < M)
                *(float2*)(C + (size_t)(row0 + 8) * EMBD + col) = make_float2(acc[mt][nt][2], acc[mt][nt][3]);
        }
    }

    // fused al epilogue: per-row partial dots with asrc/adst, quad-reduce, atomic add
    float as_[16], ad_[16];
    #pragma unroll
    for (int nt = 0; nt < 8; nt++)
        #pragma unroll
        for (int c = 0; c < 2; c++) {
            int col = bn + wc * 64 + nt * 8 + tig * 2 + c;
            as_[nt * 2 + c] = __ldg(&asrc[col]);
            ad_[nt * 2 + c] = __ldg(&adst[col]);
        }

    #pragma unroll
    for (int mt = 0; mt < 2; mt++) {
        #pragma unroll
        for (int rs = 0; rs < 2; rs++) {
            float ps0 = 0.f, ps1 = 0.f, pd0 = 0.f, pd1 = 0.f;
            #pragma unroll
            for (int nt = 0; nt < 8; nt++)
                #pragma unroll
                for (int c = 0; c < 2; c++) {
                    float v = acc[mt][nt][rs * 2 + c];
                    float a = as_[nt * 2 + c], dd = ad_[nt * 2 + c];
                    if (nt < 4) { ps0 += v * a; pd0 += v * dd; }
                    else        { ps1 += v * a; pd1 += v * dd; }
                }
            if (H == 1) { ps0 += ps1; pd0 += pd1; }
            // reduce over the 4 tig lanes (lane bits 0..1)
            #pragma unroll
            for (int o = 1; o < 4; o <<= 1) {
                ps0 += __shfl_xor_sync(0xffffffffu, ps0, o);
                pd0 += __shfl_xor_sync(0xffffffffu, pd0, o);
                if (H == 8) {
                    ps1 += __shfl_xor_sync(0xffffffffu, ps1, o);
                    pd1 += __shfl_xor_sync(0xffffffffu, pd1, o);
                }
            }
            if (tig == 0) {
                int row = bm + wr * 32 + mt * 16 + gid + rs * 8;
                if (row < M) {
                    if (H == 8) {
                        int head0 = (bn >> 5) + wc * 2;
                        atomicAdd(&ALS[row * 8 + head0], ps0);
                        atomicAdd(&ALS[row * 8 + head0 + 1], ps1);
                        atomicAdd(&ALD[row * 8 + head0], pd0);
                        atomicAdd(&ALD[row * 8 + head0 + 1], pd1);
                    } else {
                        atomicAdd(&ALS[row], ps0);
                        atomicAdd(&ALD[row], pd0);
                    }
                }
            }
        }
    }
}

// ---------------- FUSED alpha + aggregation: 4 nodes/block, 64-thread groups ----------------
template <int H, bool INTERNAL_DST>
__global__ void __launch_bounds__(256) agg_kernel(const float* __restrict__ bias,
                                                  float* __restrict__ outext) {
    const int t  = threadIdx.x;
    const int g  = t >> 6;
    const int t4 = t & 63;
    const int c0 = t4 * 4;
    const int hh = (H == 8) ? (c0 >> 5) : 0;
    const int d  = blockIdx.x * 4 + g;   // NN % 4 == 0

    const float* ALS = (H == 8) ? g_als : g_als2;
    const float* ALD = (H == 8) ? g_ald : g_ald2;

    __shared__ int   s_src[4][64];
    __shared__ float s_alpha[4][64 * H];

    const int begin = g_rowptr[d], end = g_rowptr[d + 1];
    const float aldv = ALD[d * H + ((H == 8) ? (t4 & 7) : 0)];

    float4 acc = make_float4(0.f, 0.f, 0.f, 0.f);
    float z = 0.f;

    for (int c = begin; c < end; c += 64) {
        int len = min(64, end - c);
        gbar(1 + g);
        if (t4 < len) s_src[g][t4] = g_srcs[c + t4];
        gbar(1 + g);
        if (H == 8) {
            for (int idx = t4; idx < len * 8; idx += 64) {
                int j = idx >> 3, h = idx & 7;
                s_alpha[g][idx] = __expf(lrelu(__ldg(&ALS[s_src[g][j] * 8 + h]) + aldv));
            }
        } else {
            for (int idx = t4; idx < len; idx += 64)
                s_alpha[g][idx] = __expf(lrelu(__ldg(&ALS[s_src[g][idx]]) + aldv));
        }
        gbar(1 + g);
        for (int j = 0; j < len; j++) {
            float a = s_alpha[g][j * H + hh];
            z += a;
            const float4 hv = *(const float4*)(g_h + (size_t)s_src[g][j] * EMBD + c0);
            acc.x += a * hv.x; acc.y += a * hv.y; acc.z += a * hv.z; acc.w += a * hv.w;
        }
    }

    const float inv = 1.f / (z + 1e-16f);
    const float4 bv = *(const float4*)(bias + c0);
    float4 r = make_float4(acc.x * inv + bv.x, acc.y * inv + bv.y,
                           acc.z * inv + bv.z, acc.w * inv + bv.w);
    float* dst = INTERNAL_DST ? (g_o1 + (size_t)d * EMBD + c0)
                              : (outext + (size_t)d * EMBD + c0);
    *(float4*)dst = r;
}

// ---------------- launch ----------------
extern "C" void kernel_launch(void* const* d_in, const int* in_sizes, int n_in,
                              void* d_out, int out_size) {
    const float* x   = (const float*)d_in[0];
    const void*  ei  = d_in[1];
    const float* W1  = (const float*)d_in[2];
    const float* as1 = (const float*)d_in[3];
    const float* ad1 = (const float*)d_in[4];
    const float* b1  = (const float*)d_in[5];
    const float* W2  = (const float*)d_in[6];
    const float* as2 = (const float*)d_in[7];
    const float* ad2 = (const float*)d_in[8];
    const float* b2  = (const float*)d_in[9];
    float* out = (float*)d_out;

    init_kernel<<<(NN * 8 + 255) / 256, 256>>>(ei);
    deg_kernel<<<(NE / 4 + 255) / 256, 256>>>(ei);
    scan1_kernel<<<NBLK, 256>>>();
    scan_apply_kernel<<<NBLK, 256>>>();
    scatter_kernel<<<(NE / 4 + 255) / 256, 256>>>(ei);

    dim3 gg((NN + 127) / 128, 2);
    const int AGB = NN / 4;

    // layer 1 (H=8, F=32)
    gemm_tc_kernel<8, false><<<gg, 256>>>(x, W1, as1, ad1, NN);
    agg_kernel<8, true><<<AGB, 256>>>(b1, nullptr);

    // layer 2 (H=1, F=256)
    gemm_tc_kernel<1, true><<<gg, 256>>>(nullptr, W2, as2, ad2, NN);
    agg_kernel<1, false><<<AGB, 256>>>(b2, out);
}

// round 12
// speedup vs baseline: 2.0819x; 1.0409x over previous
#include <cuda_runtime.h>
#include <cstdint>

#define NN   50000
#define EMBD 256
#define NE   800000
#define ETOT (NE + NN)
#define NBLK 196                      // ceil(NN/256)

// ---------------- static device scratch ----------------
__device__ float g_h[(size_t)NN * EMBD];
__device__ float g_o1[(size_t)NN * EMBD];
__device__ float g_als[NN * 8];       // layer-1 (H=8) logit pieces
__device__ float g_ald[NN * 8];
__device__ float g_als2[NN];          // layer-2 (H=1)
__device__ float g_ald2[NN];
__device__ int   g_rowptr[NN + 1];
__device__ int   g_cnt[NN];
__device__ int   g_srcs[ETOT];
__device__ int   g_tmp[NN];
__device__ int   g_bsum[NBLK];
__device__ int   g_is64;

__device__ __forceinline__ float lrelu(float x) { return x > 0.f ? x : 0.2f * x; }

__device__ __forceinline__ uint32_t f2tf(float f) {
    uint32_t u;
    asm("cvt.rna.tf32.f32 %0, %1;" : "=r"(u) : "f"(f));
    return u;
}

__device__ __forceinline__ void gbar(int id) {
    asm volatile("bar.sync %0, 64;" :: "r"(id) : "memory");
}

// ---------------- init: zero counters + logit accumulators + dtype probe ----------------
__global__ void init_kernel(const void* ei) {
    const int i = blockIdx.x * blockDim.x + threadIdx.x;
    const int stride = gridDim.x * blockDim.x;
    if (i < NN) { g_cnt[i] = 0; g_als2[i] = 0.f; g_ald2[i] = 0.f; }
    for (int j = i; j < NN * 8; j += stride) { g_als[j] = 0.f; g_ald[j] = 0.f; }
    if (i == 0) {
        const long long* p = (const long long*)ei;
        bool ok = true;
        #pragma unroll
        for (int k = 0; k < 8; k++) {
            long long v = p[k];
            if (v < 0 || v >= NN) ok = false;
        }
        g_is64 = ok ? 1 : 0;
    }
}

// ---------------- CSR build (4 edges / thread) ----------------
__global__ void deg_kernel(const void* __restrict__ ei) {
    int e4 = blockIdx.x * blockDim.x + threadIdx.x;
    if (e4 >= NE / 4) return;
    if (!g_is64) {
        int4 d = ((const int4*)((const int*)ei + NE))[e4];
        atomicAdd(&g_cnt[d.x], 1);
        atomicAdd(&g_cnt[d.y], 1);
        atomicAdd(&g_cnt[d.z], 1);
        atomicAdd(&g_cnt[d.w], 1);
    } else {
        const long long* p = (const long long*)ei + NE;
        #pragma unroll
        for (int k = 0; k < 4; k++) atomicAdd(&g_cnt[(int)p[e4 * 4 + k]], 1);
    }
}

__global__ void __launch_bounds__(256) scan1_kernel() {
    __shared__ int wsum[8];
    const int t = threadIdx.x, b = blockIdx.x;
    const int i = b * 256 + t;
    int v = (i < NN) ? g_cnt[i] + 1 : 0;
    int x = v;
    #pragma unroll
    for (int o = 1; o < 32; o <<= 1) {
        int y = __shfl_up_sync(0xffffffffu, x, o);
        if ((t & 31) >= o) x += y;
    }
    if ((t & 31) == 31) wsum[t >> 5] = x;
    __syncthreads();
    if (t < 8) {
        int w = wsum[t];
        #pragma unroll
        for (int o = 1; o < 8; o <<= 1) {
            int y = __shfl_up_sync(0xffu, w, o);
            if (t >= o) w += y;
        }
        wsum[t] = w;
    }
    __syncthreads();
    int incl = x + ((t >= 32) ? wsum[(t >> 5) - 1] : 0);
    if (i < NN) g_tmp[i] = incl;
    if (t == 255) g_bsum[b] = incl;
}

// merged scan2+scan3
__global__ void __launch_bounds__(256) scan_apply_kernel() {
    __shared__ int red[8];
    __shared__ int s_off;
    const int t = threadIdx.x, b = blockIdx.x;
    int v = (t < b) ? g_bsum[t] : 0;
    #pragma unroll
    for (int o = 16; o; o >>= 1) v += __shfl_xor_sync(0xffffffffu, v, o);
    if ((t & 31) == 0) red[t >> 5] = v;
    __syncthreads();
    if (t == 0) {
        int s = 0;
        #pragma unroll
        for (int ww = 0; ww < 8; ww++) s += red[ww];
        s_off = s;
        if (b == 0) g_rowptr[0] = 0;
    }
    __syncthreads();
    const int i = b * 256 + t;
    if (i < NN) {
        int rp1 = g_tmp[i] + s_off;
        g_rowptr[i + 1] = rp1;
        g_cnt[i] = 0;
        g_srcs[rp1 - 1] = i;
    }
}

__global__ void scatter_kernel(const void* __restrict__ ei) {
    int e4 = blockIdx.x * blockDim.x + threadIdx.x;
    if (e4 >= NE / 4) return;
    int s[4], d[4];
    if (!g_is64) {
        int4 sv = ((const int4*)ei)[e4];
        int4 dv = ((const int4*)((const int*)ei + NE))[e4];
        s[0] = sv.x; s[1] = sv.y; s[2] = sv.z; s[3] = sv.w;
        d[0] = dv.x; d[1] = dv.y; d[2] = dv.z; d[3] = dv.w;
    } else {
        const long long* ps = (const long long*)ei;
        const long long* pd = ps + NE;
        #pragma unroll
        for (int k = 0; k < 4; k++) { s[k] = (int)ps[e4 * 4 + k]; d[k] = (int)pd[e4 * 4 + k]; }
    }
    #pragma unroll
    for (int k = 0; k < 4; k++) {
        int pos = g_rowptr[d[k]] + atomicAdd(&g_cnt[d[k]], 1);
        g_srcs[pos] = s[k];
    }
}

// ---------------- tf32 GEMM, 2-stage double-buffered (16-wide K chunks), fused al epilogue ----
template <int H, bool INTERNAL_SRC>
__global__ void __launch_bounds__(256) gemm_tc_kernel(const float* __restrict__ Aext,
                                                      const float* __restrict__ B,
                                                      const float* __restrict__ asrc,
                                                      const float* __restrict__ adst, int M) {
    const float* A = INTERNAL_SRC ? g_o1 : Aext;
    float* C = g_h;
    float* ALS = (H == 8) ? g_als : g_als2;
    float* ALD = (H == 8) ? g_ald : g_ald2;

    __shared__ uint32_t As[2][16][129];
    __shared__ uint32_t Bs[2][16][132];

    const int t    = threadIdx.x;
    const int lane = t & 31;
    const int w    = t >> 5;
    const int wr   = w & 3;
    const int wc   = w >> 2;
    const int tig  = lane & 3;
    const int gid  = lane >> 2;
    const int bm   = blockIdx.x * 128;
    const int bn   = blockIdx.y * 128;

    float acc[2][8][4];
    #pragma unroll
    for (int mt = 0; mt < 2; mt++)
        #pragma unroll
        for (int nt = 0; nt < 8; nt++)
            #pragma unroll
            for (int c = 0; c < 4; c++) acc[mt][nt][c] = 0.f;

    const int a_r  = t >> 2;           // 0..63
    const int a_ko = (t & 3) * 4;      // 0,4,8,12

    float4 pa[2], pb[2];

    // prefetch chunk 0
    #pragma unroll
    for (int i = 0; i < 2; i++) {
        int grow = bm + a_r + i * 64;
        pa[i] = (grow < M) ? *(const float4*)(A + (size_t)grow * EMBD + a_ko)
                           : make_float4(0.f, 0.f, 0.f, 0.f);
    }
    #pragma unroll
    for (int i = 0; i < 2; i++) {
        int idx = t + i * 256;
        int kr  = idx >> 5;            // 0..15
        int c4  = (idx & 31) * 4;
        pb[i] = *(const float4*)(B + (size_t)kr * EMBD + bn + c4);
    }

    #pragma unroll 1
    for (int kc = 0; kc < 16; kc++) {
        const int p = kc & 1;
        // stage prefetched chunk into buffer p
        #pragma unroll
        for (int i = 0; i < 2; i++) {
            int r = a_r + i * 64;
            As[p][a_ko + 0][r] = f2tf(pa[i].x);
            As[p][a_ko + 1][r] = f2tf(pa[i].y);
            As[p][a_ko + 2][r] = f2tf(pa[i].z);
            As[p][a_ko + 3][r] = f2tf(pa[i].w);
        }
        #pragma unroll
        for (int i = 0; i < 2; i++) {
            int idx = t + i * 256;
            int kr  = idx >> 5;
            int c4  = (idx & 31) * 4;
            uint4 u;
            u.x = f2tf(pb[i].x); u.y = f2tf(pb[i].y); u.z = f2tf(pb[i].z); u.w = f2tf(pb[i].w);
            *(uint4*)&Bs[p][kr][c4] = u;
        }
        __syncthreads();

        // prefetch next chunk (overlaps mma)
        if (kc + 1 < 16) {
            const int kbase = (kc + 1) * 16;
            #pragma unroll
            for (int i = 0; i < 2; i++) {
                int grow = bm + a_r + i * 64;
                pa[i] = (grow < M) ? *(const float4*)(A + (size_t)grow * EMBD + kbase + a_ko)
                                   : make_float4(0.f, 0.f, 0.f, 0.f);
            }
            #pragma unroll
            for (int i = 0; i < 2; i++) {
                int idx = t + i * 256;
                int kr  = idx >> 5;
                int c4  = (idx & 31) * 4;
                pb[i] = *(const float4*)(B + (size_t)(kbase + kr) * EMBD + bn + c4);
            }
        }

        // mma over the 16-wide chunk (2 k-steps of 8)
        #pragma unroll
        for (int k0 = 0; k0 < 16; k0 += 8) {
            uint32_t af[2][4], bf[8][2];
            const int kr0 = k0 + tig, kr1 = k0 + tig + 4;
            #pragma unroll
            for (int mt = 0; mt < 2; mt++) {
                int m0 = wr * 32 + mt * 16 + gid;
                af[mt][0] = As[p][kr0][m0];
                af[mt][1] = As[p][kr0][m0 + 8];
                af[mt][2] = As[p][kr1][m0];
                af[mt][3] = As[p][kr1][m0 + 8];
            }
            #pragma unroll
            for (int nt = 0; nt < 8; nt++) {
                int n0 = wc * 64 + nt * 8 + gid;
                bf[nt][0] = Bs[p][kr0][n0];
                bf[nt][1] = Bs[p][kr1][n0];
            }
            #pragma unroll
            for (int mt = 0; mt < 2; mt++)
                #pragma unroll
                for (int nt = 0; nt < 8; nt++) {
                    asm volatile(
                        "mma.sync.aligned.m16n8k8.row.col.f32.tf32.tf32.f32 "
                        "{%0,%1,%2,%3}, {%4,%5,%6,%7}, {%8,%9}, {%0,%1,%2,%3};\n"
                        : "+f"(acc[mt][nt][0]), "+f"(acc[mt][nt][1]),
                          "+f"(acc[mt][nt][2]), "+f"(acc[mt][nt][3])
                        : "r"(af[mt][0]), "r"(af[mt][1]), "r"(af[mt][2]), "r"(af[mt][3]),
                          "r"(bf[nt][0]), "r"(bf[nt][1]));
                }
        }
    }

    // store C
    #pragma unroll
    for (int mt = 0; mt < 2; mt++) {
        int row0 = bm + wr * 32 + mt * 16 + gid;
        #pragma unroll
        for (int nt = 0; nt < 8; nt++) {
            int col = bn + wc * 64 + nt * 8 + tig * 2;
            if (row0 < M)
                *(float2*)(C + (size_t)row0 * EMBD + col) = make_float2(acc[mt][nt][0], acc[mt][nt][1]);
            if (row0 + 8 < M)
                *(float2*)(C + (size_t)(row0 + 8) * EMBD + col) = make_float2(acc[mt][nt][2], acc[mt][nt][3]);
        }
    }

    // fused al epilogue
    float as_[16], ad_[16];
    #pragma unroll
    for (int nt = 0; nt < 8; nt++)
        #pragma unroll
        for (int c = 0; c < 2; c++) {
            int col = bn + wc * 64 + nt * 8 + tig * 2 + c;
            as_[nt * 2 + c] = __ldg(&asrc[col]);
            ad_[nt * 2 + c] = __ldg(&adst[col]);
        }

    #pragma unroll
    for (int mt = 0; mt < 2; mt++) {
        #pragma unroll
        for (int rs = 0; rs < 2; rs++) {
            float ps0 = 0.f, ps1 = 0.f, pd0 = 0.f, pd1 = 0.f;
            #pragma unroll
            for (int nt = 0; nt < 8; nt++)
                #pragma unroll
                for (int c = 0; c < 2; c++) {
                    float v = acc[mt][nt][rs * 2 + c];
                    float a = as_[nt * 2 + c], dd = ad_[nt * 2 + c];
                    if (nt < 4) { ps0 += v * a; pd0 += v * dd; }
                    else        { ps1 += v * a; pd1 += v * dd; }
                }
            if (H == 1) { ps0 += ps1; pd0 += pd1; }
            #pragma unroll
            for (int o = 1; o < 4; o <<= 1) {
                ps0 += __shfl_xor_sync(0xffffffffu, ps0, o);
                pd0 += __shfl_xor_sync(0xffffffffu, pd0, o);
                if (H == 8) {
                    ps1 += __shfl_xor_sync(0xffffffffu, ps1, o);
                    pd1 += __shfl_xor_sync(0xffffffffu, pd1, o);
                }
            }
            if (tig == 0) {
                int row = bm + wr * 32 + mt * 16 + gid + rs * 8;
                if (row < M) {
                    if (H == 8) {
                        int head0 = (bn >> 5) + wc * 2;
                        atomicAdd(&ALS[row * 8 + head0], ps0);
                        atomicAdd(&ALS[row * 8 + head0 + 1], ps1);
                        atomicAdd(&ALD[row * 8 + head0], pd0);
                        atomicAdd(&ALD[row * 8 + head0 + 1], pd1);
                    } else {
                        atomicAdd(&ALS[row], ps0);
                        atomicAdd(&ALD[row], pd0);
                    }
                }
            }
        }
    }
}

// ---------------- FUSED alpha + aggregation: 4 nodes/block, 64-thread groups ----------------
template <int H, bool INTERNAL_DST>
__global__ void __launch_bounds__(256) agg_kernel(const float* __restrict__ bias,
                                                  float* __restrict__ outext) {
    const int t  = threadIdx.x;
    const int g  = t >> 6;
    const int t4 = t & 63;
    const int c0 = t4 * 4;
    const int hh = (H == 8) ? (c0 >> 5) : 0;
    const int d  = blockIdx.x * 4 + g;   // NN % 4 == 0

    const float* ALS = (H == 8) ? g_als : g_als2;
    const float* ALD = (H == 8) ? g_ald : g_ald2;

    __shared__ int   s_src[4][64];
    __shared__ float s_alpha[4][64 * H];

    const int begin = g_rowptr[d], end = g_rowptr[d + 1];
    const float aldv = ALD[d * H + ((H == 8) ? (t4 & 7) : 0)];

    float4 acc = make_float4(0.f, 0.f, 0.f, 0.f);
    float z = 0.f;

    for (int c = begin; c < end; c += 64) {
        int len = min(64, end - c);
        gbar(1 + g);
        if (t4 < len) s_src[g][t4] = g_srcs[c + t4];
        gbar(1 + g);
        if (H == 8) {
            for (int idx = t4; idx < len * 8; idx += 64) {
                int j = idx >> 3, h = idx & 7;
                s_alpha[g][idx] = __expf(lrelu(__ldg(&ALS[s_src[g][j] * 8 + h]) + aldv));
            }
        } else {
            for (int idx = t4; idx < len; idx += 64)
                s_alpha[g][idx] = __expf(lrelu(__ldg(&ALS[s_src[g][idx]]) + aldv));
        }
        gbar(1 + g);
        for (int j = 0; j < len; j++) {
            float a = s_alpha[g][j * H + hh];
            z += a;
            const float4 hv = *(const float4*)(g_h + (size_t)s_src[g][j] * EMBD + c0);
            acc.x += a * hv.x; acc.y += a * hv.y; acc.z += a * hv.z; acc.w += a * hv.w;
        }
    }

    const float inv = 1.f / (z + 1e-16f);
    const float4 bv = *(const float4*)(bias + c0);
    float4 r = make_float4(acc.x * inv + bv.x, acc.y * inv + bv.y,
                           acc.z * inv + bv.z, acc.w * inv + bv.w);
    float* dst = INTERNAL_DST ? (g_o1 + (size_t)d * EMBD + c0)
                              : (outext + (size_t)d * EMBD + c0);
    *(float4*)dst = r;
}

// ---------------- launch ----------------
extern "C" void kernel_launch(void* const* d_in, const int* in_sizes, int n_in,
                              void* d_out, int out_size) {
    const float* x   = (const float*)d_in[0];
    const void*  ei  = d_in[1];
    const float* W1  = (const float*)d_in[2];
    const float* as1 = (const float*)d_in[3];
    const float* ad1 = (const float*)d_in[4];
    const float* b1  = (const float*)d_in[5];
    const float* W2  = (const float*)d_in[6];
    const float* as2 = (const float*)d_in[7];
    const float* ad2 = (const float*)d_in[8];
    const float* b2  = (const float*)d_in[9];
    float* out = (float*)d_out;

    init_kernel<<<(NN * 8 + 255) / 256, 256>>>(ei);
    deg_kernel<<<(NE / 4 + 255) / 256, 256>>>(ei);
    scan1_kernel<<<NBLK, 256>>>();
    scan_apply_kernel<<<NBLK, 256>>>();
    scatter_kernel<<<(NE / 4 + 255) / 256, 256>>>(ei);

    dim3 gg((NN + 127) / 128, 2);
    const int AGB = NN / 4;

    // layer 1 (H=8, F=32)
    gemm_tc_kernel<8, false><<<gg, 256>>>(x, W1, as1, ad1, NN);
    agg_kernel<8, true><<<AGB, 256>>>(b1, nullptr);

    // layer 2 (H=1, F=256)
    gemm_tc_kernel<1, true><<<gg, 256>>>(nullptr, W2, as2, ad2, NN);
    agg_kernel<1, false><<<AGB, 256>>>(b2, out);
}

// round 13
// speedup vs baseline: 2.0838x; 1.0009x over previous
#include <cuda_runtime.h>
#include <cstdint>

#define NN   50000
#define EMBD 256
#define NE   800000
#define ETOT (NE + NN)
#define NBLK 196                      // ceil(NN/256)

// ---------------- static device scratch ----------------
__device__ float g_h[(size_t)NN * EMBD];
__device__ float g_o1[(size_t)NN * EMBD];
__device__ float g_als[NN * 8];       // layer-1 (H=8) logit pieces
__device__ float g_ald[NN * 8];
__device__ float g_als2[NN];          // layer-2 (H=1)
__device__ float g_ald2[NN];
__device__ int   g_rowptr[NN + 1];
__device__ int   g_cnt[NN];
__device__ int   g_srcs[ETOT];
__device__ int   g_tmp[NN];
__device__ int   g_bsum[NBLK];
__device__ int   g_is64;

__device__ __forceinline__ float lrelu(float x) { return x > 0.f ? x : 0.2f * x; }

__device__ __forceinline__ uint32_t f2tf(float f) {
    uint32_t u;
    asm("cvt.rna.tf32.f32 %0, %1;" : "=r"(u) : "f"(f));
    return u;
}

__device__ __forceinline__ void gbar(int id) {
    asm volatile("bar.sync %0, 64;" :: "r"(id) : "memory");
}

// ---------------- init: zero counters + logit accumulators + dtype probe ----------------
__global__ void init_kernel(const void* ei) {
    const int i = blockIdx.x * blockDim.x + threadIdx.x;
    const int stride = gridDim.x * blockDim.x;
    if (i < NN) { g_cnt[i] = 0; g_als2[i] = 0.f; g_ald2[i] = 0.f; }
    for (int j = i; j < NN * 8; j += stride) { g_als[j] = 0.f; g_ald[j] = 0.f; }
    if (i == 0) {
        const long long* p = (const long long*)ei;
        bool ok = true;
        #pragma unroll
        for (int k = 0; k < 8; k++) {
            long long v = p[k];
            if (v < 0 || v >= NN) ok = false;
        }
        g_is64 = ok ? 1 : 0;
    }
}

// ---------------- CSR build (4 edges / thread) ----------------
__global__ void deg_kernel(const void* __restrict__ ei) {
    int e4 = blockIdx.x * blockDim.x + threadIdx.x;
    if (e4 >= NE / 4) return;
    if (!g_is64) {
        int4 d = ((const int4*)((const int*)ei + NE))[e4];
        atomicAdd(&g_cnt[d.x], 1);
        atomicAdd(&g_cnt[d.y], 1);
        atomicAdd(&g_cnt[d.z], 1);
        atomicAdd(&g_cnt[d.w], 1);
    } else {
        const long long* p = (const long long*)ei + NE;
        #pragma unroll
        for (int k = 0; k < 4; k++) atomicAdd(&g_cnt[(int)p[e4 * 4 + k]], 1);
    }
}

__global__ void __launch_bounds__(256) scan1_kernel() {
    __shared__ int wsum[8];
    const int t = threadIdx.x, b = blockIdx.x;
    const int i = b * 256 + t;
    int v = (i < NN) ? g_cnt[i] + 1 : 0;
    int x = v;
    #pragma unroll
    for (int o = 1; o < 32; o <<= 1) {
        int y = __shfl_up_sync(0xffffffffu, x, o);
        if ((t & 31) >= o) x += y;
    }
    if ((t & 31) == 31) wsum[t >> 5] = x;
    __syncthreads();
    if (t < 8) {
        int w = wsum[t];
        #pragma unroll
        for (int o = 1; o < 8; o <<= 1) {
            int y = __shfl_up_sync(0xffu, w, o);
            if (t >= o) w += y;
        }
        wsum[t] = w;
    }
    __syncthreads();
    int incl = x + ((t >= 32) ? wsum[(t >> 5) - 1] : 0);
    if (i < NN) g_tmp[i] = incl;
    if (t == 255) g_bsum[b] = incl;
}

// merged scan2+scan3
__global__ void __launch_bounds__(256) scan_apply_kernel() {
    __shared__ int red[8];
    __shared__ int s_off;
    const int t = threadIdx.x, b = blockIdx.x;
    int v = (t < b) ? g_bsum[t] : 0;
    #pragma unroll
    for (int o = 16; o; o >>= 1) v += __shfl_xor_sync(0xffffffffu, v, o);
    if ((t & 31) == 0) red[t >> 5] = v;
    __syncthreads();
    if (t == 0) {
        int s = 0;
        #pragma unroll
        for (int ww = 0; ww < 8; ww++) s += red[ww];
        s_off = s;
        if (b == 0) g_rowptr[0] = 0;
    }
    __syncthreads();
    const int i = b * 256 + t;
    if (i < NN) {
        int rp1 = g_tmp[i] + s_off;
        g_rowptr[i + 1] = rp1;
        g_cnt[i] = 0;
        g_srcs[rp1 - 1] = i;
    }
}

__global__ void scatter_kernel(const void* __restrict__ ei) {
    int e4 = blockIdx.x * blockDim.x + threadIdx.x;
    if (e4 >= NE / 4) return;
    int s[4], d[4];
    if (!g_is64) {
        int4 sv = ((const int4*)ei)[e4];
        int4 dv = ((const int4*)((const int*)ei + NE))[e4];
        s[0] = sv.x; s[1] = sv.y; s[2] = sv.z; s[3] = sv.w;
        d[0] = dv.x; d[1] = dv.y; d[2] = dv.z; d[3] = dv.w;
    } else {
        const long long* ps = (const long long*)ei;
        const long long* pd = ps + NE;
        #pragma unroll
        for (int k = 0; k < 4; k++) { s[k] = (int)ps[e4 * 4 + k]; d[k] = (int)pd[e4 * 4 + k]; }
    }
    #pragma unroll
    for (int k = 0; k < 4; k++) {
        int pos = g_rowptr[d[k]] + atomicAdd(&g_cnt[d[k]], 1);
        g_srcs[pos] = s[k];
    }
}

// ---------------- tf32 GEMM, 2-stage double-buffered (16-wide K chunks), fused al epilogue ----
template <int H, bool INTERNAL_SRC>
__global__ void __launch_bounds__(256) gemm_tc_kernel(const float* __restrict__ Aext,
                                                      const float* __restrict__ B,
                                                      const float* __restrict__ asrc,
                                                      const float* __restrict__ adst, int M) {
    const float* A = INTERNAL_SRC ? g_o1 : Aext;
    float* C = g_h;
    float* ALS = (H == 8) ? g_als : g_als2;
    float* ALD = (H == 8) ? g_ald : g_ald2;

    __shared__ uint32_t As[2][16][129];
    __shared__ uint32_t Bs[2][16][132];

    const int t    = threadIdx.x;
    const int lane = t & 31;
    const int w    = t >> 5;
    const int wr   = w & 3;
    const int wc   = w >> 2;
    const int tig  = lane & 3;
    const int gid  = lane >> 2;
    const int bm   = blockIdx.x * 128;
    const int bn   = blockIdx.y * 128;

    float acc[2][8][4];
    #pragma unroll
    for (int mt = 0; mt < 2; mt++)
        #pragma unroll
        for (int nt = 0; nt < 8; nt++)
            #pragma unroll
            for (int c = 0; c < 4; c++) acc[mt][nt][c] = 0.f;

    const int a_r  = t >> 2;           // 0..63
    const int a_ko = (t & 3) * 4;      // 0,4,8,12

    float4 pa[2], pb[2];

    // prefetch chunk 0
    #pragma unroll
    for (int i = 0; i < 2; i++) {
        int grow = bm + a_r + i * 64;
        pa[i] = (grow < M) ? *(const float4*)(A + (size_t)grow * EMBD + a_ko)
                           : make_float4(0.f, 0.f, 0.f, 0.f);
    }
    #pragma unroll
    for (int i = 0; i < 2; i++) {
        int idx = t + i * 256;
        int kr  = idx >> 5;            // 0..15
        int c4  = (idx & 31) * 4;
        pb[i] = *(const float4*)(B + (size_t)kr * EMBD + bn + c4);
    }

    #pragma unroll 1
    for (int kc = 0; kc < 16; kc++) {
        const int p = kc & 1;
        // stage prefetched chunk into buffer p
        #pragma unroll
        for (int i = 0; i < 2; i++) {
            int r = a_r + i * 64;
            As[p][a_ko + 0][r] = f2tf(pa[i].x);
            As[p][a_ko + 1][r] = f2tf(pa[i].y);
            As[p][a_ko + 2][r] = f2tf(pa[i].z);
            As[p][a_ko + 3][r] = f2tf(pa[i].w);
        }
        #pragma unroll
        for (int i = 0; i < 2; i++) {
            int idx = t + i * 256;
            int kr  = idx >> 5;
            int c4  = (idx & 31) * 4;
            uint4 u;
            u.x = f2tf(pb[i].x); u.y = f2tf(pb[i].y); u.z = f2tf(pb[i].z); u.w = f2tf(pb[i].w);
            *(uint4*)&Bs[p][kr][c4] = u;
        }
        __syncthreads();

        // prefetch next chunk (overlaps mma)
        if (kc + 1 < 16) {
            const int kbase = (kc + 1) * 16;
            #pragma unroll
            for (int i = 0; i < 2; i++) {
                int grow = bm + a_r + i * 64;
                pa[i] = (grow < M) ? *(const float4*)(A + (size_t)grow * EMBD + kbase + a_ko)
                                   : make_float4(0.f, 0.f, 0.f, 0.f);
            }
            #pragma unroll
            for (int i = 0; i < 2; i++) {
                int idx = t + i * 256;
                int kr  = idx >> 5;
                int c4  = (idx & 31) * 4;
                pb[i] = *(const float4*)(B + (size_t)(kbase + kr) * EMBD + bn + c4);
            }
        }

        // mma over the 16-wide chunk (2 k-steps of 8)
        #pragma unroll
        for (int k0 = 0; k0 < 16; k0 += 8) {
            uint32_t af[2][4], bf[8][2];
            const int kr0 = k0 + tig, kr1 = k0 + tig + 4;
            #pragma unroll
            for (int mt = 0; mt < 2; mt++) {
                int m0 = wr * 32 + mt * 16 + gid;
                af[mt][0] = As[p][kr0][m0];
                af[mt][1] = As[p][kr0][m0 + 8];
                af[mt][2] = As[p][kr1][m0];
                af[mt][3] = As[p][kr1][m0 + 8];
            }
            #pragma unroll
            for (int nt = 0; nt < 8; nt++) {
                int n0 = wc * 64 + nt * 8 + gid;
                bf[nt][0] = Bs[p][kr0][n0];
                bf[nt][1] = Bs[p][kr1][n0];
            }
            #pragma unroll
            for (int mt = 0; mt < 2; mt++)
                #pragma unroll
                for (int nt = 0; nt < 8; nt++) {
                    asm volatile(
                        "mma.sync.aligned.m16n8k8.row.col.f32.tf32.tf32.f32 "
                        "{%0,%1,%2,%3}, {%4,%5,%6,%7}, {%8,%9}, {%0,%1,%2,%3};\n"
                        : "+f"(acc[mt][nt][0]), "+f"(acc[mt][nt][1]),
                          "+f"(acc[mt][nt][2]), "+f"(acc[mt][nt][3])
                        : "r"(af[mt][0]), "r"(af[mt][1]), "r"(af[mt][2]), "r"(af[mt][3]),
                          "r"(bf[nt][0]), "r"(bf[nt][1]));
                }
        }
    }

    // store C
    #pragma unroll
    for (int mt = 0; mt < 2; mt++) {
        int row0 = bm + wr * 32 + mt * 16 + gid;
        #pragma unroll
        for (int nt = 0; nt < 8; nt++) {
            int col = bn + wc * 64 + nt * 8 + tig * 2;
            if (row0 < M)
                *(float2*)(C + (size_t)row0 * EMBD + col) = make_float2(acc[mt][nt][0], acc[mt][nt][1]);
            if (row0 + 8 < M)
                *(float2*)(C + (size_t)(row0 + 8) * EMBD + col) = make_float2(acc[mt][nt][2], acc[mt][nt][3]);
        }
    }

    // fused al epilogue
    float as_[16], ad_[16];
    #pragma unroll
    for (int nt = 0; nt < 8; nt++)
        #pragma unroll
        for (int c = 0; c < 2; c++) {
            int col = bn + wc * 64 + nt * 8 + tig * 2 + c;
            as_[nt * 2 + c] = __ldg(&asrc[col]);
            ad_[nt * 2 + c] = __ldg(&adst[col]);
        }

    #pragma unroll
    for (int mt = 0; mt < 2; mt++) {
        #pragma unroll
        for (int rs = 0; rs < 2; rs++) {
            float ps0 = 0.f, ps1 = 0.f, pd0 = 0.f, pd1 = 0.f;
            #pragma unroll
            for (int nt = 0; nt < 8; nt++)
                #pragma unroll
                for (int c = 0; c < 2; c++) {
                    float v = acc[mt][nt][rs * 2 + c];
                    float a = as_[nt * 2 + c], dd = ad_[nt * 2 + c];
                    if (nt < 4) { ps0 += v * a; pd0 += v * dd; }
                    else        { ps1 += v * a; pd1 += v * dd; }
                }
            if (H == 1) { ps0 += ps1; pd0 += pd1; }
            #pragma unroll
            for (int o = 1; o < 4; o <<= 1) {
                ps0 += __shfl_xor_sync(0xffffffffu, ps0, o);
                pd0 += __shfl_xor_sync(0xffffffffu, pd0, o);
                if (H == 8) {
                    ps1 += __shfl_xor_sync(0xffffffffu, ps1, o);
                    pd1 += __shfl_xor_sync(0xffffffffu, pd1, o);
                }
            }
            if (tig == 0) {
                int row = bm + wr * 32 + mt * 16 + gid + rs * 8;
                if (row < M) {
                    if (H == 8) {
                        int head0 = (bn >> 5) + wc * 2;
                        atomicAdd(&ALS[row * 8 + head0], ps0);
                        atomicAdd(&ALS[row * 8 + head0 + 1], ps1);
                        atomicAdd(&ALD[row * 8 + head0], pd0);
                        atomicAdd(&ALD[row * 8 + head0 + 1], pd1);
                    } else {
                        atomicAdd(&ALS[row], ps0);
                        atomicAdd(&ALD[row], pd0);
                    }
                }
            }
        }
    }
}

// ---------------- FUSED alpha + aggregation: 4 nodes/block, 64-thread groups ----------------
template <int H, bool INTERNAL_DST>
__global__ void __launch_bounds__(256) agg_kernel(const float* __restrict__ bias,
                                                  float* __restrict__ outext) {
    const int t  = threadIdx.x;
    const int g  = t >> 6;
    const int t4 = t & 63;
    const int c0 = t4 * 4;
    const int hh = (H == 8) ? (c0 >> 5) : 0;
    const int d  = blockIdx.x * 4 + g;   // NN % 4 == 0

    const float* ALS = (H == 8) ? g_als : g_als2;
    const float* ALD = (H == 8) ? g_ald : g_ald2;

    __shared__ int   s_src[4][64];
    __shared__ float s_alpha[4][64 * H];

    const int begin = g_rowptr[d], end = g_rowptr[d + 1];
    const float aldv = ALD[d * H + ((H == 8) ? (t4 & 7) : 0)];

    float4 acc = make_float4(0.f, 0.f, 0.f, 0.f);
    float z = 0.f;

    for (int c = begin; c < end; c += 64) {
        int len = min(64, end - c);
        gbar(1 + g);
        if (t4 < len) s_src[g][t4] = g_srcs[c + t4];
        gbar(1 + g);
        if (H == 8) {
            for (int idx = t4; idx < len * 8; idx += 64) {
                int j = idx >> 3, h = idx & 7;
                s_alpha[g][idx] = __expf(lrelu(__ldg(&ALS[s_src[g][j] * 8 + h]) + aldv));
            }
        } else {
            for (int idx = t4; idx < len; idx += 64)
                s_alpha[g][idx] = __expf(lrelu(__ldg(&ALS[s_src[g][idx]]) + aldv));
        }
        gbar(1 + g);
        for (int j = 0; j < len; j++) {
            float a = s_alpha[g][j * H + hh];
            z += a;
            const float4 hv = *(const float4*)(g_h + (size_t)s_src[g][j] * EMBD + c0);
            acc.x += a * hv.x; acc.y += a * hv.y; acc.z += a * hv.z; acc.w += a * hv.w;
        }
    }

    const float inv = 1.f / (z + 1e-16f);
    const float4 bv = *(const float4*)(bias + c0);
    float4 r = make_float4(acc.x * inv + bv.x, acc.y * inv + bv.y,
                           acc.z * inv + bv.z, acc.w * inv + bv.w);
    float* dst = INTERNAL_DST ? (g_o1 + (size_t)d * EMBD + c0)
                              : (outext + (size_t)d * EMBD + c0);
    *(float4*)dst = r;
}

// ---------------- launch ----------------
extern "C" void kernel_launch(void* const* d_in, const int* in_sizes, int n_in,
                              void* d_out, int out_size) {
    const float* x   = (const float*)d_in[0];
    const void*  ei  = d_in[1];
    const float* W1  = (const float*)d_in[2];
    const float* as1 = (const float*)d_in[3];
    const float* ad1 = (const float*)d_in[4];
    const float* b1  = (const float*)d_in[5];
    const float* W2  = (const float*)d_in[6];
    const float* as2 = (const float*)d_in[7];
    const float* ad2 = (const float*)d_in[8];
    const float* b2  = (const float*)d_in[9];
    float* out = (float*)d_out;

    init_kernel<<<(NN * 8 + 255) / 256, 256>>>(ei);
    deg_kernel<<<(NE / 4 + 255) / 256, 256>>>(ei);
    scan1_kernel<<<NBLK, 256>>>();
    scan_apply_kernel<<<NBLK, 256>>>();
    scatter_kernel<<<(NE / 4 + 255) / 256, 256>>>(ei);

    dim3 gg((NN + 127) / 128, 2);
    const int AGB = NN / 4;

    // layer 1 (H=8, F=32)
    gemm_tc_kernel<8, false><<<gg, 256>>>(x, W1, as1, ad1, NN);
    agg_kernel<8, true><<<AGB, 256>>>(b1, nullptr);

    // layer 2 (H=1, F=256)
    gemm_tc_kernel<1, true><<<gg, 256>>>(nullptr, W2, as2, ad2, NN);
    agg_kernel<1, false><<<AGB, 256>>>(b2, out);
}

// round 14
// speedup vs baseline: 2.0854x; 1.0008x over previous
#include <cuda_runtime.h>
#include <cstdint>

#define NN   50000
#define EMBD 256
#define NE   800000
#define ETOT (NE + NN)
#define NBLK 196                      // ceil(NN/256)

// ---------------- static device scratch ----------------
__device__ float g_h[(size_t)NN * EMBD];
__device__ float g_o1[(size_t)NN * EMBD];
__device__ float g_als[NN * 8];       // layer-1 (H=8) logit pieces
__device__ float g_ald[NN * 8];
__device__ float g_als2[NN];          // layer-2 (H=1)
__device__ float g_ald2[NN];
__device__ int   g_rowptr[NN + 1];
__device__ int   g_cnt[NN];
__device__ int   g_srcs[ETOT];
__device__ int   g_tmp[NN];
__device__ int   g_bsum[NBLK];
__device__ int   g_is64;

__device__ __forceinline__ float lrelu(float x) { return x > 0.f ? x : 0.2f * x; }

__device__ __forceinline__ uint32_t f2tf(float f) {
    uint32_t u;
    asm("cvt.rna.tf32.f32 %0, %1;" : "=r"(u) : "f"(f));
    return u;
}

__device__ __forceinline__ void gbar(int id) {
    asm volatile("bar.sync %0, 64;" :: "r"(id) : "memory");
}

// ---------------- init: zero counters + logit accumulators + dtype probe ----------------
__global__ void init_kernel(const void* ei) {
    const int i = blockIdx.x * blockDim.x + threadIdx.x;
    const int stride = gridDim.x * blockDim.x;
    if (i < NN) { g_cnt[i] = 0; g_als2[i] = 0.f; g_ald2[i] = 0.f; }
    for (int j = i; j < NN * 8; j += stride) { g_als[j] = 0.f; g_ald[j] = 0.f; }
    if (i == 0) {
        const long long* p = (const long long*)ei;
        bool ok = true;
        #pragma unroll
        for (int k = 0; k < 8; k++) {
            long long v = p[k];
            if (v < 0 || v >= NN) ok = false;
        }
        g_is64 = ok ? 1 : 0;
    }
}

// ---------------- CSR build (4 edges / thread) ----------------
__global__ void deg_kernel(const void* __restrict__ ei) {
    int e4 = blockIdx.x * blockDim.x + threadIdx.x;
    if (e4 >= NE / 4) return;
    if (!g_is64) {
        int4 d = ((const int4*)((const int*)ei + NE))[e4];
        atomicAdd(&g_cnt[d.x], 1);
        atomicAdd(&g_cnt[d.y], 1);
        atomicAdd(&g_cnt[d.z], 1);
        atomicAdd(&g_cnt[d.w], 1);
    } else {
        const long long* p = (const long long*)ei + NE;
        #pragma unroll
        for (int k = 0; k < 4; k++) atomicAdd(&g_cnt[(int)p[e4 * 4 + k]], 1);
    }
}

__global__ void __launch_bounds__(256) scan1_kernel() {
    __shared__ int wsum[8];
    const int t = threadIdx.x, b = blockIdx.x;
    const int i = b * 256 + t;
    int v = (i < NN) ? g_cnt[i] + 1 : 0;
    int x = v;
    #pragma unroll
    for (int o = 1; o < 32; o <<= 1) {
        int y = __shfl_up_sync(0xffffffffu, x, o);
        if ((t & 31) >= o) x += y;
    }
    if ((t & 31) == 31) wsum[t >> 5] = x;
    __syncthreads();
    if (t < 8) {
        int w = wsum[t];
        #pragma unroll
        for (int o = 1; o < 8; o <<= 1) {
            int y = __shfl_up_sync(0xffu, w, o);
            if (t >= o) w += y;
        }
        wsum[t] = w;
    }
    __syncthreads();
    int incl = x + ((t >= 32) ? wsum[(t >> 5) - 1] : 0);
    if (i < NN) g_tmp[i] = incl;
    if (t == 255) g_bsum[b] = incl;
}

// merged scan2+scan3
__global__ void __launch_bounds__(256) scan_apply_kernel() {
    __shared__ int red[8];
    __shared__ int s_off;
    const int t = threadIdx.x, b = blockIdx.x;
    int v = (t < b) ? g_bsum[t] : 0;
    #pragma unroll
    for (int o = 16; o; o >>= 1) v += __shfl_xor_sync(0xffffffffu, v, o);
    if ((t & 31) == 0) red[t >> 5] = v;
    __syncthreads();
    if (t == 0) {
        int s = 0;
        #pragma unroll
        for (int ww = 0; ww < 8; ww++) s += red[ww];
        s_off = s;
        if (b == 0) g_rowptr[0] = 0;
    }
    __syncthreads();
    const int i = b * 256 + t;
    if (i < NN) {
        int rp1 = g_tmp[i] + s_off;
        g_rowptr[i + 1] = rp1;
        g_cnt[i] = 0;
        g_srcs[rp1 - 1] = i;
    }
}

__global__ void scatter_kernel(const void* __restrict__ ei) {
    int e4 = blockIdx.x * blockDim.x + threadIdx.x;
    if (e4 >= NE / 4) return;
    int s[4], d[4];
    if (!g_is64) {
        int4 sv = ((const int4*)ei)[e4];
        int4 dv = ((const int4*)((const int*)ei + NE))[e4];
        s[0] = sv.x; s[1] = sv.y; s[2] = sv.z; s[3] = sv.w;
        d[0] = dv.x; d[1] = dv.y; d[2] = dv.z; d[3] = dv.w;
    } else {
        const long long* ps = (const long long*)ei;
        const long long* pd = ps + NE;
        #pragma unroll
        for (int k = 0; k < 4; k++) { s[k] = (int)ps[e4 * 4 + k]; d[k] = (int)pd[e4 * 4 + k]; }
    }
    #pragma unroll
    for (int k = 0; k < 4; k++) {
        int pos = g_rowptr[d[k]] + atomicAdd(&g_cnt[d[k]], 1);
        g_srcs[pos] = s[k];
    }
}

// ---------------- tf32 GEMM, 2-stage double-buffered (16-wide K chunks), fused al epilogue ----
template <int H, bool INTERNAL_SRC>
__global__ void __launch_bounds__(256) gemm_tc_kernel(const float* __restrict__ Aext,
                                                      const float* __restrict__ B,
                                                      const float* __restrict__ asrc,
                                                      const float* __restrict__ adst, int M) {
    const float* A = INTERNAL_SRC ? g_o1 : Aext;
    float* C = g_h;
    float* ALS = (H == 8) ? g_als : g_als2;
    float* ALD = (H == 8) ? g_ald : g_ald2;

    __shared__ uint32_t As[2][16][129];
    __shared__ uint32_t Bs[2][16][132];

    const int t    = threadIdx.x;
    const int lane = t & 31;
    const int w    = t >> 5;
    const int wr   = w & 3;
    const int wc   = w >> 2;
    const int tig  = lane & 3;
    const int gid  = lane >> 2;
    const int bm   = blockIdx.x * 128;
    const int bn   = blockIdx.y * 128;

    float acc[2][8][4];
    #pragma unroll
    for (int mt = 0; mt < 2; mt++)
        #pragma unroll
        for (int nt = 0; nt < 8; nt++)
            #pragma unroll
            for (int c = 0; c < 4; c++) acc[mt][nt][c] = 0.f;

    const int a_r  = t >> 2;           // 0..63
    const int a_ko = (t & 3) * 4;      // 0,4,8,12

    float4 pa[2], pb[2];

    // prefetch chunk 0
    #pragma unroll
    for (int i = 0; i < 2; i++) {
        int grow = bm + a_r + i * 64;
        pa[i] = (grow < M) ? *(const float4*)(A + (size_t)grow * EMBD + a_ko)
                           : make_float4(0.f, 0.f, 0.f, 0.f);
    }
    #pragma unroll
    for (int i = 0; i < 2; i++) {
        int idx = t + i * 256;
        int kr  = idx >> 5;            // 0..15
        int c4  = (idx & 31) * 4;
        pb[i] = *(const float4*)(B + (size_t)kr * EMBD + bn + c4);
    }

    #pragma unroll 1
    for (int kc = 0; kc < 16; kc++) {
        const int p = kc & 1;
        // stage prefetched chunk into buffer p
        #pragma unroll
        for (int i = 0; i < 2; i++) {
            int r = a_r + i * 64;
            As[p][a_ko + 0][r] = f2tf(pa[i].x);
            As[p][a_ko + 1][r] = f2tf(pa[i].y);
            As[p][a_ko + 2][r] = f2tf(pa[i].z);
            As[p][a_ko + 3][r] = f2tf(pa[i].w);
        }
        #pragma unroll
        for (int i = 0; i < 2; i++) {
            int idx = t + i * 256;
            int kr  = idx >> 5;
            int c4  = (idx & 31) * 4;
            uint4 u;
            u.x = f2tf(pb[i].x); u.y = f2tf(pb[i].y); u.z = f2tf(pb[i].z); u.w = f2tf(pb[i].w);
            *(uint4*)&Bs[p][kr][c4] = u;
        }
        __syncthreads();

        // prefetch next chunk (overlaps mma)
        if (kc + 1 < 16) {
            const int kbase = (kc + 1) * 16;
            #pragma unroll
            for (int i = 0; i < 2; i++) {
                int grow = bm + a_r + i * 64;
                pa[i] = (grow < M) ? *(const float4*)(A + (size_t)grow * EMBD + kbase + a_ko)
                                   : make_float4(0.f, 0.f, 0.f, 0.f);
            }
            #pragma unroll
            for (int i = 0; i < 2; i++) {
                int idx = t + i * 256;
                int kr  = idx >> 5;
                int c4  = (idx & 31) * 4;
                pb[i] = *(const float4*)(B + (size_t)(kbase + kr) * EMBD + bn + c4);
            }
        }

        // mma over the 16-wide chunk (2 k-steps of 8)
        #pragma unroll
        for (int k0 = 0; k0 < 16; k0 += 8) {
            uint32_t af[2][4], bf[8][2];
            const int kr0 = k0 + tig, kr1 = k0 + tig + 4;
            #pragma unroll
            for (int mt = 0; mt < 2; mt++) {
                int m0 = wr * 32 + mt * 16 + gid;
                af[mt][0] = As[p][kr0][m0];
                af[mt][1] = As[p][kr0][m0 + 8];
                af[mt][2] = As[p][kr1][m0];
                af[mt][3] = As[p][kr1][m0 + 8];
            }
            #pragma unroll
            for (int nt = 0; nt < 8; nt++) {
                int n0 = wc * 64 + nt * 8 + gid;
                bf[nt][0] = Bs[p][kr0][n0];
                bf[nt][1] = Bs[p][kr1][n0];
            }
            #pragma unroll
            for (int mt = 0; mt < 2; mt++)
                #pragma unroll
                for (int nt = 0; nt < 8; nt++) {
                    asm volatile(
                        "mma.sync.aligned.m16n8k8.row.col.f32.tf32.tf32.f32 "
                        "{%0,%1,%2,%3}, {%4,%5,%6,%7}, {%8,%9}, {%0,%1,%2,%3};\n"
                        : "+f"(acc[mt][nt][0]), "+f"(acc[mt][nt][1]),
                          "+f"(acc[mt][nt][2]), "+f"(acc[mt][nt][3])
                        : "r"(af[mt][0]), "r"(af[mt][1]), "r"(af[mt][2]), "r"(af[mt][3]),
                          "r"(bf[nt][0]), "r"(bf[nt][1]));
                }
        }
    }

    // store C
    #pragma unroll
    for (int mt = 0; mt < 2; mt++) {
        int row0 = bm + wr * 32 + mt * 16 + gid;
        #pragma unroll
        for (int nt = 0; nt < 8; nt++) {
            int col = bn + wc * 64 + nt * 8 + tig * 2;
            if (row0 < M)
                *(float2*)(C + (size_t)row0 * EMBD + col) = make_float2(acc[mt][nt][0], acc[mt][nt][1]);
            if (row0 + 8 < M)
                *(float2*)(C + (size_t)(row0 + 8) * EMBD + col) = make_float2(acc[mt][nt][2], acc[mt][nt][3]);
        }
    }

    // fused al epilogue
    float as_[16], ad_[16];
    #pragma unroll
    for (int nt = 0; nt < 8; nt++)
        #pragma unroll
        for (int c = 0; c < 2; c++) {
            int col = bn + wc * 64 + nt * 8 + tig * 2 + c;
            as_[nt * 2 + c] = __ldg(&asrc[col]);
            ad_[nt * 2 + c] = __ldg(&adst[col]);
        }

    #pragma unroll
    for (int mt = 0; mt < 2; mt++) {
        #pragma unroll
        for (int rs = 0; rs < 2; rs++) {
            float ps0 = 0.f, ps1 = 0.f, pd0 = 0.f, pd1 = 0.f;
            #pragma unroll
            for (int nt = 0; nt < 8; nt++)
                #pragma unroll
                for (int c = 0; c < 2; c++) {
                    float v = acc[mt][nt][rs * 2 + c];
                    float a = as_[nt * 2 + c], dd = ad_[nt * 2 + c];
                    if (nt < 4) { ps0 += v * a; pd0 += v * dd; }
                    else        { ps1 += v * a; pd1 += v * dd; }
                }
            if (H == 1) { ps0 += ps1; pd0 += pd1; }
            #pragma unroll
            for (int o = 1; o < 4; o <<= 1) {
                ps0 += __shfl_xor_sync(0xffffffffu, ps0, o);
                pd0 += __shfl_xor_sync(0xffffffffu, pd0, o);
                if (H == 8) {
                    ps1 += __shfl_xor_sync(0xffffffffu, ps1, o);
                    pd1 += __shfl_xor_sync(0xffffffffu, pd1, o);
                }
            }
            if (tig == 0) {
                int row = bm + wr * 32 + mt * 16 + gid + rs * 8;
                if (row < M) {
                    if (H == 8) {
                        int head0 = (bn >> 5) + wc * 2;
                        atomicAdd(&ALS[row * 8 + head0], ps0);
                        atomicAdd(&ALS[row * 8 + head0 + 1], ps1);
                        atomicAdd(&ALD[row * 8 + head0], pd0);
                        atomicAdd(&ALD[row * 8 + head0 + 1], pd1);
                    } else {
                        atomicAdd(&ALS[row], ps0);
                        atomicAdd(&ALD[row], pd0);
                    }
                }
            }
        }
    }
}

// ---------------- FUSED alpha + aggregation: 4 nodes/block, 64-thread groups ----------------
template <int H, bool INTERNAL_DST>
__global__ void __launch_bounds__(256) agg_kernel(const float* __restrict__ bias,
                                                  float* __restrict__ outext) {
    const int t  = threadIdx.x;
    const int g  = t >> 6;
    const int t4 = t & 63;
    const int c0 = t4 * 4;
    const int hh = (H == 8) ? (c0 >> 5) : 0;
    const int d  = blockIdx.x * 4 + g;   // NN % 4 == 0

    const float* ALS = (H == 8) ? g_als : g_als2;
    const float* ALD = (H == 8) ? g_ald : g_ald2;

    __shared__ int   s_src[4][64];
    __shared__ float s_alpha[4][64 * H];

    const int begin = g_rowptr[d], end = g_rowptr[d + 1];
    const float aldv = ALD[d * H + ((H == 8) ? (t4 & 7) : 0)];

    float4 acc = make_float4(0.f, 0.f, 0.f, 0.f);
    float z = 0.f;

    for (int c = begin; c < end; c += 64) {
        int len = min(64, end - c);
        gbar(1 + g);
        if (t4 < len) s_src[g][t4] = g_srcs[c + t4];
        gbar(1 + g);
        if (H == 8) {
            for (int idx = t4; idx < len * 8; idx += 64) {
                int j = idx >> 3, h = idx & 7;
                s_alpha[g][idx] = __expf(lrelu(__ldg(&ALS[s_src[g][j] * 8 + h]) + aldv));
            }
        } else {
            for (int idx = t4; idx < len; idx += 64)
                s_alpha[g][idx] = __expf(lrelu(__ldg(&ALS[s_src[g][idx]]) + aldv));
        }
        gbar(1 + g);
        for (int j = 0; j < len; j++) {
            float a = s_alpha[g][j * H + hh];
            z += a;
            const float4 hv = *(const float4*)(g_h + (size_t)s_src[g][j] * EMBD + c0);
            acc.x += a * hv.x; acc.y += a * hv.y; acc.z += a * hv.z; acc.w += a * hv.w;
        }
    }

    const float inv = 1.f / (z + 1e-16f);
    const float4 bv = *(const float4*)(bias + c0);
    float4 r = make_float4(acc.x * inv + bv.x, acc.y * inv + bv.y,
                           acc.z * inv + bv.z, acc.w * inv + bv.w);
    float* dst = INTERNAL_DST ? (g_o1 + (size_t)d * EMBD + c0)
                              : (outext + (size_t)d * EMBD + c0);
    *(float4*)dst = r;
}

// ---------------- launch ----------------
extern "C" void kernel_launch(void* const* d_in, const int* in_sizes, int n_in,
                              void* d_out, int out_size) {
    const float* x   = (const float*)d_in[0];
    const void*  ei  = d_in[1];
    const float* W1  = (const float*)d_in[2];
    const float* as1 = (const float*)d_in[3];
    const float* ad1 = (const float*)d_in[4];
    const float* b1  = (const float*)d_in[5];
    const float* W2  = (const float*)d_in[6];
    const float* as2 = (const float*)d_in[7];
    const float* ad2 = (const float*)d_in[8];
    const float* b2  = (const float*)d_in[9];
    float* out = (float*)d_out;

    init_kernel<<<(NN * 8 + 255) / 256, 256>>>(ei);
    deg_kernel<<<(NE / 4 + 255) / 256, 256>>>(ei);
    scan1_kernel<<<NBLK, 256>>>();
    scan_apply_kernel<<<NBLK, 256>>>();
    scatter_kernel<<<(NE / 4 + 255) / 256, 256>>>(ei);

    dim3 gg((NN + 127) / 128, 2);
    const int AGB = NN / 4;

    // layer 1 (H=8, F=32)
    gemm_tc_kernel<8, false><<<gg, 256>>>(x, W1, as1, ad1, NN);
    agg_kernel<8, true><<<AGB, 256>>>(b1, nullptr);

    // layer 2 (H=1, F=256)
    gemm_tc_kernel<1, true><<<gg, 256>>>(nullptr, W2, as2, ad2, NN);
    agg_kernel<1, false><<<AGB, 256>>>(b2, out);
}